// round 14
// baseline (speedup 1.0000x reference)
#include <cuda_runtime.h>
#include <cuda.h>
#include <cuda_bf16.h>
#include <cuda_fp16.h>
#include <math.h>
#include <stdint.h>

#define SEQ     2048
#define DMODEL  2048
#define NHEADS  16
#define HD2     128
#define QKVN    (3*DMODEL)   // 6144

// tcgen05/TMA exist only in the arch-specific (sm_103a) device pass.
#if !defined(__CUDA_ARCH__) || defined(__CUDA_ARCH_FEAT_SM103_ALL)
#define TC_HELPERS_VISIBLE 1
#endif
#if defined(__CUDA_ARCH__) && defined(__CUDA_ARCH_FEAT_SM103_ALL)
#define TC_RUN 1
#endif

// ---------------- scratch (static device globals; no allocations) ----------
__device__ __nv_bfloat16 g_xh[(size_t)SEQ * DMODEL],  g_xl[(size_t)SEQ * DMODEL];
__device__ __nv_bfloat16 g_wqh[(size_t)QKVN * DMODEL], g_wql[(size_t)QKVN * DMODEL];
__device__ __nv_bfloat16 g_woh[(size_t)DMODEL * DMODEL], g_wol[(size_t)DMODEL * DMODEL];
__device__ __nv_bfloat16 g_yh[(size_t)SEQ * DMODEL],  g_yl[(size_t)SEQ * DMODEL];
__device__ __nv_bfloat16 g_qh[(size_t)NHEADS * SEQ * HD2], g_ql[(size_t)NHEADS * SEQ * HD2];
__device__ __nv_bfloat16 g_kh[(size_t)NHEADS * SEQ * HD2], g_kl[(size_t)NHEADS * SEQ * HD2];
__device__ __half g_vth[(size_t)NHEADS * HD2 * SEQ], g_vtl[(size_t)NHEADS * HD2 * SEQ];

// =============================== PTX helpers ===============================
#ifdef TC_HELPERS_VISIBLE
__device__ __forceinline__ uint32_t smem_u32(const void* p) {
    uint32_t a;
    asm("{ .reg .u64 t; cvta.to.shared.u64 t, %1; cvt.u32.u64 %0, t; }"
        : "=r"(a) : "l"(p));
    return a;
}
__device__ __forceinline__ bool elect_one() {
    uint32_t pred;
    asm volatile("{\n\t.reg .pred p;\n\telect.sync _|p, 0xFFFFFFFF;\n\t"
                 "selp.b32 %0, 1, 0, p;\n\t}" : "=r"(pred));
    return pred != 0;
}
__device__ __forceinline__ uint32_t ctarank() {
    uint32_t r;
    asm("mov.u32 %0, %%cluster_ctarank;" : "=r"(r));
    return r;
}
__device__ __forceinline__ void cluster_sync() {
    asm volatile("barrier.cluster.arrive.aligned;" ::: "memory");
    asm volatile("barrier.cluster.wait.aligned;" ::: "memory");
}
__device__ __forceinline__ void mbar_init(uint32_t a, uint32_t cnt) {
    asm volatile("mbarrier.init.shared.b64 [%0], %1;" :: "r"(a), "r"(cnt) : "memory");
}
__device__ __forceinline__ void mbar_expect_tx(uint32_t a, uint32_t bytes) {
    asm volatile("mbarrier.arrive.expect_tx.shared.b64 _, [%0], %1;"
                 :: "r"(a), "r"(bytes) : "memory");
}
// arrive+expect on the LEADER CTA's barrier (bit24 cleared) from any rank
__device__ __forceinline__ void expect_tx_leader(uint32_t a, uint32_t bytes) {
    asm volatile(
        "{\n\t.reg .b32 lb;\n\tand.b32 lb, %0, 0xFEFFFFFF;\n\t"
        "mbarrier.arrive.expect_tx.shared::cluster.b64 _, [lb], %1;\n\t}"
        :: "r"(a), "r"(bytes) : "memory");
}
__device__ __forceinline__ void mbar_wait(uint32_t a, uint32_t phase) {
    asm volatile(
        "{\n\t.reg .pred P;\n\t"
        "WL_%=:\n\t"
        "mbarrier.try_wait.parity.acquire.cta.shared::cta.b64 P, [%0], %1, 0x989680;\n\t"
        "@P bra WD_%=;\n\t"
        "bra WL_%=;\n\t"
        "WD_%=:\n\t}" :: "r"(a), "r"(phase) : "memory");
}
__device__ __forceinline__ void tma_2d(uint32_t dst, const void* tmap,
                                       int cx, int cy, uint32_t mbar) {
    asm volatile(
        "cp.async.bulk.tensor.2d.shared::cta.global.tile.mbarrier::complete_tx::bytes "
        "[%0], [%1, {%2, %3}], [%4];"
        :: "r"(dst), "l"(tmap), "r"(cx), "r"(cy), "r"(mbar) : "memory");
}
// cg2 TMA: completion tx arrives on the leader CTA's barrier
__device__ __forceinline__ void tma_2d_cg2(uint32_t dst, const void* tmap,
                                           int cx, int cy, uint32_t mbar) {
    asm volatile(
        "{\n\t.reg .b32 lb;\n\tand.b32 lb, %4, 0xFEFFFFFF;\n\t"
        "cp.async.bulk.tensor.2d.cta_group::2.shared::cluster.global.tile"
        ".mbarrier::complete_tx::bytes [%0], [%1, {%2, %3}], [lb];\n\t}"
        :: "r"(dst), "l"(tmap), "r"(cx), "r"(cy), "r"(mbar) : "memory");
}
__device__ __forceinline__ void tc_alloc(uint32_t dst_smem, uint32_t ncols) {
    asm volatile("tcgen05.alloc.cta_group::1.sync.aligned.shared::cta.b32 [%0], %1;"
                 :: "r"(dst_smem), "r"(ncols) : "memory");
}
__device__ __forceinline__ void tc_alloc_cg2(uint32_t dst_smem, uint32_t ncols) {
    asm volatile("tcgen05.alloc.cta_group::2.sync.aligned.shared::cta.b32 [%0], %1;"
                 :: "r"(dst_smem), "r"(ncols) : "memory");
}
__device__ __forceinline__ void tc_relinq() {
    asm volatile("tcgen05.relinquish_alloc_permit.cta_group::1.sync.aligned;");
}
__device__ __forceinline__ void tc_relinq_cg2() {
    asm volatile("tcgen05.relinquish_alloc_permit.cta_group::2.sync.aligned;");
}
__device__ __forceinline__ void tc_dealloc(uint32_t tmem, uint32_t ncols) {
    asm volatile("tcgen05.dealloc.cta_group::1.sync.aligned.b32 %0, %1;"
                 :: "r"(tmem), "r"(ncols));
}
__device__ __forceinline__ void tc_dealloc_cg2(uint32_t tmem, uint32_t ncols) {
    asm volatile("tcgen05.dealloc.cta_group::2.sync.aligned.b32 %0, %1;"
                 :: "r"(tmem), "r"(ncols));
}
__device__ __forceinline__ void tc_commit(uint32_t mbar) {
    asm volatile("tcgen05.commit.cta_group::1.mbarrier::arrive::one.shared::cluster.b64 [%0];"
                 :: "r"(mbar) : "memory");
}
__device__ __forceinline__ void tc_commit_mc2(uint32_t mbar, uint16_t mask) {
    asm volatile(
        "tcgen05.commit.cta_group::2.mbarrier::arrive::one.shared::cluster"
        ".multicast::cluster.b64 [%0], %1;"
        :: "r"(mbar), "h"(mask) : "memory");
}
__device__ __forceinline__ void tc_fence_after() {
    asm volatile("tcgen05.fence::after_thread_sync;" ::: "memory");
}
__device__ __forceinline__ void tc_fence_before() {
    asm volatile("tcgen05.fence::before_thread_sync;" ::: "memory");
}
__device__ __forceinline__ void fence_async_shared() {
    asm volatile("fence.proxy.async.shared::cta;" ::: "memory");
}
__device__ __forceinline__ void tc_wait_ld() {
    asm volatile("tcgen05.wait::ld.sync.aligned;" ::: "memory");
}
__device__ __forceinline__ void tc_wait_st() {
    asm volatile("tcgen05.wait::st.sync.aligned;" ::: "memory");
}
__device__ __forceinline__ void mma_f16_ss(uint32_t d, uint64_t ad, uint64_t bd,
                                           uint32_t idesc, uint32_t en) {
    asm volatile(
        "{\n\t.reg .pred p;\n\tsetp.ne.u32 p, %4, 0;\n\t"
        "tcgen05.mma.cta_group::1.kind::f16 [%0], %1, %2, %3, {%5,%5,%5,%5}, p;\n\t}"
        :: "r"(d), "l"(ad), "l"(bd), "r"(idesc), "r"(en), "r"(0u) : "memory");
}
__device__ __forceinline__ void mma_f16_ss_cg2(uint32_t d, uint64_t ad, uint64_t bd,
                                               uint32_t idesc, uint32_t en) {
    asm volatile(
        "{\n\t.reg .pred p;\n\tsetp.ne.u32 p, %4, 0;\n\t"
        "tcgen05.mma.cta_group::2.kind::f16 [%0], %1, %2, %3, "
        "{%5,%5,%5,%5,%5,%5,%5,%5}, p;\n\t}"
        :: "r"(d), "l"(ad), "l"(bd), "r"(idesc), "r"(en), "r"(0u) : "memory");
}
__device__ __forceinline__ void mma_f16_ts(uint32_t d, uint32_t at, uint64_t bd,
                                           uint32_t idesc, uint32_t en) {
    asm volatile(
        "{\n\t.reg .pred p;\n\tsetp.ne.u32 p, %4, 0;\n\t"
        "tcgen05.mma.cta_group::1.kind::f16 [%0], [%1], %2, %3, {%5,%5,%5,%5}, p;\n\t}"
        :: "r"(d), "r"(at), "l"(bd), "r"(idesc), "r"(en), "r"(0u) : "memory");
}
__device__ __forceinline__ void tc_ld32(uint32_t* r, uint32_t a) {
    asm volatile(
        "tcgen05.ld.sync.aligned.32x32b.x32.b32 "
        "{%0,%1,%2,%3,%4,%5,%6,%7,%8,%9,%10,%11,%12,%13,%14,%15,"
        "%16,%17,%18,%19,%20,%21,%22,%23,%24,%25,%26,%27,%28,%29,%30,%31}, [%32];"
        : "=r"(r[0]),"=r"(r[1]),"=r"(r[2]),"=r"(r[3]),"=r"(r[4]),"=r"(r[5]),"=r"(r[6]),"=r"(r[7]),
          "=r"(r[8]),"=r"(r[9]),"=r"(r[10]),"=r"(r[11]),"=r"(r[12]),"=r"(r[13]),"=r"(r[14]),"=r"(r[15]),
          "=r"(r[16]),"=r"(r[17]),"=r"(r[18]),"=r"(r[19]),"=r"(r[20]),"=r"(r[21]),"=r"(r[22]),"=r"(r[23]),
          "=r"(r[24]),"=r"(r[25]),"=r"(r[26]),"=r"(r[27]),"=r"(r[28]),"=r"(r[29]),"=r"(r[30]),"=r"(r[31])
        : "r"(a));
}
__device__ __forceinline__ void tc_st16(uint32_t a, const uint32_t* r) {
    asm volatile(
        "tcgen05.st.sync.aligned.32x32b.x16.b32 [%0], "
        "{%1,%2,%3,%4,%5,%6,%7,%8,%9,%10,%11,%12,%13,%14,%15,%16};"
        :: "r"(a),
           "r"(r[0]),"r"(r[1]),"r"(r[2]),"r"(r[3]),"r"(r[4]),"r"(r[5]),"r"(r[6]),"r"(r[7]),
           "r"(r[8]),"r"(r[9]),"r"(r[10]),"r"(r[11]),"r"(r[12]),"r"(r[13]),"r"(r[14]),"r"(r[15])
        : "memory");
}
__device__ __forceinline__ uint64_t make_desc(uint32_t addr) {
    const uint64_t base = (2ull << 61) | (1ull << 46) | (64ull << 32) | (1ull << 16); // SW128
    return base | ((addr >> 4) & 0x3FFF);
}
#endif // TC_HELPERS_VISIBLE

// ===================== split fp32 -> bf16 hi/lo ============================
__global__ void split_f32(const float* __restrict__ in,
                          __nv_bfloat16* __restrict__ hi,
                          __nv_bfloat16* __restrict__ lo, int n4) {
    int i = blockIdx.x * blockDim.x + threadIdx.x;
    if (i >= n4) return;
    float4 v = ((const float4*)in)[i];
    float f[4] = {v.x, v.y, v.z, v.w};
    union { __nv_bfloat16 b[4]; uint2 u; } H, L;
#pragma unroll
    for (int j = 0; j < 4; j++) {
        H.b[j] = __float2bfloat16(f[j]);
        L.b[j] = __float2bfloat16(f[j] - __bfloat162float(H.b[j]));
    }
    ((uint2*)hi)[i] = H.u;
    ((uint2*)lo)[i] = L.u;
}

// ============ GEMM (cg2 pair: M=256 x N=256, per-CTA 128 rows) =============
// grid.x = M tiles (cluster pairs along x), grid.y = N tiles
// Warp-specialized mainloop: warp0(rank0)=MMA consumer, warp1(both)=TMA producer.
#define BM 128
#define BN 256
#define BKE 64
#define STAGE_BYTES (64*1024)            // per-CTA per-stage (A 32K + B-half 32K)
#define OFF_AH 0
#define OFF_AL (16*1024)
#define OFF_BH (32*1024)
#define OFF_BL (48*1024)
#define NSTG 3
#define GEMM_SMEM (NSTG*STAGE_BYTES + 1024)

#ifdef TC_RUN
__device__ __forceinline__ void gemm_mainloop_cg2(
        const CUtensorMap* tAh, const CUtensorMap* tAl,
        const CUtensorMap* tBh, const CUtensorMap* tBl,
        uint32_t tile_u32, const uint32_t* F, const uint32_t* E,
        uint32_t tmem, int bm, int bnme, int K, uint32_t rank, int wid) {
    const uint32_t IDESC = (1u << 4) | (1u << 7) | (1u << 10)
                         | ((BN / 8) << 17) | ((256 / 16) << 24);   // M=256 cg2
    const int NS = K / BKE;

    if (wid == 1) {
        // ---------------- producer warp (both ranks) ----------------
        if (!elect_one()) return;
        uint32_t phE[NSTG] = {0, 0, 0};
        for (int s = 0; s < NS; s++) {
            const int b = s % NSTG;
            if (s >= NSTG) { mbar_wait(E[b], phE[b]); phE[b] ^= 1; }
            const uint32_t base = tile_u32 + (uint32_t)b * STAGE_BYTES;
            const int k0 = s * BKE;
            expect_tx_leader(F[b], 65536);        // this rank's 64KB share
            tma_2d_cg2(base + OFF_AH, tAh, k0, bm,   F[b]);
            tma_2d_cg2(base + OFF_AL, tAl, k0, bm,   F[b]);
            tma_2d_cg2(base + OFF_BH, tBh, k0, bnme, F[b]);
            tma_2d_cg2(base + OFF_BL, tBl, k0, bnme, F[b]);
        }
        // final drain: last commit covers all MMAs (in-order queue)
        const int lb = (NS - 1) % NSTG;
        mbar_wait(E[lb], phE[lb]);
    } else if (wid == 0 && rank == 0) {
        // ---------------- consumer warp (leader CTA only) ----------------
        if (!elect_one()) return;
        uint32_t phF[NSTG] = {0, 0, 0};
        for (int s = 0; s < NS; s++) {
            const int b = s % NSTG;
            mbar_wait(F[b], phF[b]); phF[b] ^= 1;
            const uint32_t bb = tile_u32 + (uint32_t)b * STAGE_BYTES;
            uint64_t dAh = make_desc(bb + OFF_AH);
            uint64_t dAl = make_desc(bb + OFF_AL);
            uint64_t dBh = make_desc(bb + OFF_BH);
            uint64_t dBl = make_desc(bb + OFF_BL);
#pragma unroll
            for (int ks = 0; ks < 4; ks++) {
                mma_f16_ss_cg2(tmem, dAh + ks * 2, dBh + ks * 2, IDESC,
                               (s != 0) || (ks != 0));
                mma_f16_ss_cg2(tmem, dAh + ks * 2, dBl + ks * 2, IDESC, 1);
                mma_f16_ss_cg2(tmem, dAl + ks * 2, dBh + ks * 2, IDESC, 1);
            }
            tc_commit_mc2(E[b], 0x3);
        }
    }
}
#endif

// fp32 register-tiled fallback core (portable pass only)
template <typename EPI>
__device__ __forceinline__ void gemm_fallback(
        char* smem, int tid, int bm, int bn, int K,
        const __nv_bfloat16* Ah, const __nv_bfloat16* Al,
        const __nv_bfloat16* Bh, const __nv_bfloat16* Bl, EPI epi) {
    float* As = (float*)smem;
    float* Bs = As + 16 * 132;
    const int tx   = tid & 15;
    const int ty   = tid >> 4;
    const int lrow = tid >> 2;
    const int lcol = (tid & 3) << 2;

    for (int nh = 0; nh < 2; nh++) {
        const int bnn = bn + nh * 128;
        float acc[8][8];
#pragma unroll
        for (int i = 0; i < 8; i++)
#pragma unroll
            for (int j = 0; j < 8; j++) acc[i][j] = 0.0f;

        for (int k0 = 0; k0 < K; k0 += 16) {
            __syncthreads();
#pragma unroll
            for (int r = 0; r < 2; r++) {
                const int row = lrow + r * 64;
                const size_t ao = (size_t)(bm + row) * K + k0 + lcol;
                const size_t bo = (size_t)(bnn + row) * K + k0 + lcol;
                uint2 uah = *(const uint2*)(Ah + ao), ual = *(const uint2*)(Al + ao);
                uint2 ubh = *(const uint2*)(Bh + bo), ubl = *(const uint2*)(Bl + bo);
                const __nv_bfloat16* ah4 = (const __nv_bfloat16*)&uah;
                const __nv_bfloat16* al4 = (const __nv_bfloat16*)&ual;
                const __nv_bfloat16* bh4 = (const __nv_bfloat16*)&ubh;
                const __nv_bfloat16* bl4 = (const __nv_bfloat16*)&ubl;
#pragma unroll
                for (int j = 0; j < 4; j++) {
                    As[(lcol + j) * 132 + row] =
                        __bfloat162float(ah4[j]) + __bfloat162float(al4[j]);
                    Bs[(lcol + j) * 132 + row] =
                        __bfloat162float(bh4[j]) + __bfloat162float(bl4[j]);
                }
            }
            __syncthreads();

#pragma unroll
            for (int k = 0; k < 16; k++) {
                float4 a0 = *(const float4*)&As[k * 132 + ty * 8];
                float4 a1 = *(const float4*)&As[k * 132 + ty * 8 + 4];
                float4 b0 = *(const float4*)&Bs[k * 132 + tx * 8];
                float4 b1 = *(const float4*)&Bs[k * 132 + tx * 8 + 4];
                float av[8] = {a0.x, a0.y, a0.z, a0.w, a1.x, a1.y, a1.z, a1.w};
                float bv[8] = {b0.x, b0.y, b0.z, b0.w, b1.x, b1.y, b1.z, b1.w};
#pragma unroll
                for (int i = 0; i < 8; i++)
#pragma unroll
                    for (int j = 0; j < 8; j++)
                        acc[i][j] = fmaf(av[i], bv[j], acc[i][j]);
            }
        }
        __syncthreads();
#pragma unroll
        for (int i = 0; i < 8; i++)
#pragma unroll
            for (int j = 0; j < 8; j++)
                epi(bm + ty * 8 + i, bnn + tx * 8 + j, acc[i][j]);
    }
}

// ===== GEMM 1: qkv = x @ Wqkv^T (cg2), epilogue splits into q/k/vT =========
__global__ __launch_bounds__(256, 1) __cluster_dims__(2, 1, 1)
void gemm_qkv(const __grid_constant__ CUtensorMap tAh,
              const __grid_constant__ CUtensorMap tAl,
              const __grid_constant__ CUtensorMap tBh,
              const __grid_constant__ CUtensorMap tBl,
              const __nv_bfloat16* __restrict__ Ah,
              const __nv_bfloat16* __restrict__ Al,
              const __nv_bfloat16* __restrict__ Bh,
              const __nv_bfloat16* __restrict__ Bl,
              __nv_bfloat16* __restrict__ qh, __nv_bfloat16* __restrict__ ql,
              __nv_bfloat16* __restrict__ kh, __nv_bfloat16* __restrict__ kl,
              __half* __restrict__ vth, __half* __restrict__ vtl, int K) {
    extern __shared__ __align__(16) char smem[];
    const int tid = threadIdx.x;
    const int bm = blockIdx.x * BM;          // M along x (cluster pairs)
    const int bn = blockIdx.y * BN;          // N along y

#ifdef TC_RUN
    __shared__ uint32_t s_tmem;
    __shared__ __align__(8) unsigned long long s_mbar[2 * NSTG];

    const int wid = tid >> 5;
    const int lane = tid & 31;
    const uint32_t rank = ctarank();

    const uint32_t smem_base = smem_u32(smem);
    const uint32_t tile_u32  = (smem_base + 1023) & ~1023u;
    const uint32_t mb = smem_u32(&s_mbar[0]);
    uint32_t F[NSTG] = {mb, mb + 8, mb + 16};
    uint32_t E[NSTG] = {mb + 24, mb + 32, mb + 40};

    if (wid == 0) { tc_alloc_cg2(smem_u32(&s_tmem), 256); tc_relinq_cg2(); }
    if (tid == 0) {
#pragma unroll
        for (int i = 0; i < NSTG; i++) { mbar_init(F[i], 2); mbar_init(E[i], 1); }
        fence_async_shared();
    }
    __syncthreads();
    cluster_sync();
    const uint32_t tmem = s_tmem;

    if (wid < 2)
        gemm_mainloop_cg2(&tAh, &tAl, &tBh, &tBl, tile_u32, F, E,
                          tmem, bm, bn + (int)rank * 128, K, rank, wid);
    __syncthreads();
    tc_fence_after();

    // epilogue: each 128-col half = one head of one of q/k/v (own 128 rows)
    {
        const int g = wid >> 2;
        const int sub = wid & 3;
        const int srow = bm + sub * 32 + lane;
        const int gcolb = bn + g * 128;
        const int region = gcolb >> 11;          // 0=q, 1=k, 2=v
        const int head = (gcolb & 2047) >> 7;

#pragma unroll
        for (int cb = 0; cb < 4; cb++) {
            uint32_t r[32];
            tc_ld32(r, tmem + g * 128 + cb * 32);
            tc_wait_ld();

            if (region < 2) {
                __nv_bfloat16* dh = region ? kh : qh;
                __nv_bfloat16* dl = region ? kl : ql;
                uint32_t hp[16], lp[16];
#pragma unroll
                for (int t = 0; t < 16; t++) {
                    float f0 = __uint_as_float(r[2 * t]);
                    float f1 = __uint_as_float(r[2 * t + 1]);
                    uint32_t h;
                    asm("cvt.rn.bf16x2.f32 %0, %1, %2;" : "=r"(h) : "f"(f1), "f"(f0));
                    float fh0 = __uint_as_float(h << 16);
                    float fh1 = __uint_as_float(h & 0xffff0000u);
                    uint32_t l;
                    asm("cvt.rn.bf16x2.f32 %0, %1, %2;"
                        : "=r"(l) : "f"(f1 - fh1), "f"(f0 - fh0));
                    hp[t] = h; lp[t] = l;
                }
                size_t base = ((size_t)head * SEQ + srow) * 128 + cb * 32;
                uint4* dh4 = (uint4*)(dh + base);
                uint4* dl4 = (uint4*)(dl + base);
#pragma unroll
                for (int q = 0; q < 4; q++) {
                    dh4[q] = make_uint4(hp[4*q], hp[4*q+1], hp[4*q+2], hp[4*q+3]);
                    dl4[q] = make_uint4(lp[4*q], lp[4*q+1], lp[4*q+2], lp[4*q+3]);
                }
            } else {
#pragma unroll
                for (int c = 0; c < 32; c++) {
                    float f = __uint_as_float(r[c]);
                    __half hi = __float2half_rn(f);
                    __half lo = __float2half_rn(f - __half2float(hi));
                    size_t idx = ((size_t)head * 128 + cb * 32 + c) * SEQ + srow;
                    vth[idx] = hi;
                    vtl[idx] = lo;
                }
            }
        }
    }
    tc_fence_before();
    __syncthreads();
    if (wid == 0) tc_dealloc_cg2(tmem, 256);
    cluster_sync();

#else
    gemm_fallback(smem, tid, bm, bn, K, Ah, Al, Bh, Bl,
        [&](int row, int gcol, float f) {
            int region = gcol >> 11;
            int head = (gcol & 2047) >> 7;
            int c = gcol & 127;
            if (region < 2) {
                __nv_bfloat16* dh = region ? kh : qh;
                __nv_bfloat16* dl = region ? kl : ql;
                size_t o = ((size_t)head * SEQ + row) * 128 + c;
                __nv_bfloat16 hi = __float2bfloat16(f);
                dh[o] = hi;
                dl[o] = __float2bfloat16(f - __bfloat162float(hi));
            } else {
                size_t o = ((size_t)head * 128 + c) * SEQ + row;
                __half hi = __float2half_rn(f);
                vth[o] = hi;
                vtl[o] = __float2half_rn(f - __half2float(hi));
            }
        });
#endif
}

// ============== GEMM 2: out = y @ Wo^T (cg2), fp32 epilogue ================
__global__ __launch_bounds__(256, 1) __cluster_dims__(2, 1, 1)
void gemm_tma(const __grid_constant__ CUtensorMap tAh,
              const __grid_constant__ CUtensorMap tAl,
              const __grid_constant__ CUtensorMap tBh,
              const __grid_constant__ CUtensorMap tBl,
              const __nv_bfloat16* __restrict__ Ah,
              const __nv_bfloat16* __restrict__ Al,
              const __nv_bfloat16* __restrict__ Bh,
              const __nv_bfloat16* __restrict__ Bl,
              float* __restrict__ C, int N, int K) {
    extern __shared__ __align__(16) char smem[];
    const int tid = threadIdx.x;
    const int bm = blockIdx.x * BM;          // M along x (cluster pairs)
    const int bn = blockIdx.y * BN;          // N along y

#ifdef TC_RUN
    __shared__ uint32_t s_tmem;
    __shared__ __align__(8) unsigned long long s_mbar[2 * NSTG];

    const int wid = tid >> 5;
    const int lane = tid & 31;
    const uint32_t rank = ctarank();

    const uint32_t smem_base = smem_u32(smem);
    const uint32_t tile_u32  = (smem_base + 1023) & ~1023u;
    const uint32_t mb = smem_u32(&s_mbar[0]);
    uint32_t F[NSTG] = {mb, mb + 8, mb + 16};
    uint32_t E[NSTG] = {mb + 24, mb + 32, mb + 40};

    if (wid == 0) { tc_alloc_cg2(smem_u32(&s_tmem), 256); tc_relinq_cg2(); }
    if (tid == 0) {
#pragma unroll
        for (int i = 0; i < NSTG; i++) { mbar_init(F[i], 2); mbar_init(E[i], 1); }
        fence_async_shared();
    }
    __syncthreads();
    cluster_sync();
    const uint32_t tmem = s_tmem;

    if (wid < 2)
        gemm_mainloop_cg2(&tAh, &tAl, &tBh, &tBl, tile_u32, F, E,
                          tmem, bm, bn + (int)rank * 128, K, rank, wid);
    __syncthreads();
    tc_fence_after();

    {
        const int g = wid >> 2;
        const int sub = wid & 3;
        float* crow = C + (size_t)(bm + sub * 32 + lane) * N + bn + g * 128;
#pragma unroll
        for (int cb = 0; cb < 4; cb++) {
            uint32_t r[32];
            tc_ld32(r, tmem + g * 128 + cb * 32);
            tc_wait_ld();
#pragma unroll
            for (int c = 0; c < 32; c += 4) {
                float4 o = make_float4(__uint_as_float(r[c]), __uint_as_float(r[c + 1]),
                                       __uint_as_float(r[c + 2]), __uint_as_float(r[c + 3]));
                *(float4*)(crow + cb * 32 + c) = o;
            }
        }
    }
    tc_fence_before();
    __syncthreads();
    if (wid == 0) tc_dealloc_cg2(tmem, 256);
    cluster_sync();

#else
    gemm_fallback(smem, tid, bm, bn, K, Ah, Al, Bh, Bl,
        [&](int row, int gcol, float f) {
            C[(size_t)row * N + gcol] = f;
        });
#endif
}

// ============ tcgen05 differential flash attention + fused GN ==============
#define AQ1H 0
#define AQ1L (16*1024)
#define AQ2H (32*1024)
#define AQ2L (48*1024)
#define KBUF0 (64*1024)
#define KBUF1 (96*1024)
#define VBUF0 (128*1024)
#define VBUF1 (160*1024)
#define ATT_DYN (193*1024)
// TMEM cols: O1 0-127 | O2 128-255 | S1 256-319 | S2 320-383
//            P1 384-415 | P2 416-447   (P in fp16)

__global__ __launch_bounds__(512, 1)
void attn_tc(const __grid_constant__ CUtensorMap tQh,
             const __grid_constant__ CUtensorMap tQl,
             const __grid_constant__ CUtensorMap tKh,
             const __grid_constant__ CUtensorMap tKl,
             const __grid_constant__ CUtensorMap tVh,
             const __grid_constant__ CUtensorMap tVl,
             const __nv_bfloat16* __restrict__ Qh, const __nv_bfloat16* __restrict__ Ql,
             const __nv_bfloat16* __restrict__ Kh, const __nv_bfloat16* __restrict__ Kl,
             const __half* __restrict__ Vth, const __half* __restrict__ Vtl,
             const float* __restrict__ lq1, const float* __restrict__ lk1,
             const float* __restrict__ lq2, const float* __restrict__ lk2,
             const float* __restrict__ gamma, const float* __restrict__ beta,
             __nv_bfloat16* __restrict__ yh, __nv_bfloat16* __restrict__ yl) {
    extern __shared__ __align__(16) char smem[];
    const int tid = threadIdx.x;
    const int h = blockIdx.y;
    const int qb = gridDim.x - 1 - blockIdx.x;
    const int q0 = qb * 128;
    const float lambda_init = 0.8f - 0.6f * expf(-0.3f * 12.0f);

#ifdef TC_RUN
    __shared__ uint32_t s_tmem;
    __shared__ __align__(8) unsigned long long s_mbar[7];
    __shared__ float sLAM[128], sGG[128], sGB[128];
    __shared__ float sL[2][128];
    __shared__ float pS[128][2], pQ[128][2];

    const int wid = tid >> 5;
    const int lane = tid & 31;
    const int sub   = wid & 3;
    const int strm  = (wid >> 2) & 1;
    const int chalf = (wid >> 3) & 1;
    const int row = sub * 32 + lane;

    const uint32_t smem_base = smem_u32(smem);
    const uint32_t tile_u32  = (smem_base + 1023) & ~1023u;
    char* tile = smem + (tile_u32 - smem_base);
    const uint32_t QB  = smem_u32(&s_mbar[0]);
    const uint32_t SB  = QB + 8;
    const uint32_t PVB = QB + 16;
    const uint32_t KF[2] = {QB + 24, QB + 32};
    const uint32_t VF[2] = {QB + 40, QB + 48};

    if (wid == 0) { tc_alloc(smem_u32(&s_tmem), 512); tc_relinq(); }
    if (tid == 0) {
        mbar_init(QB, 1); mbar_init(SB, 1); mbar_init(PVB, 1);
        mbar_init(KF[0], 1); mbar_init(KF[1], 1);
        mbar_init(VF[0], 1); mbar_init(VF[1], 1);
        fence_async_shared();
    }
    if (tid < 128) {
        sLAM[tid] = expf(lq1[tid] * lk1[tid]) - expf(lq2[tid] * lk2[tid]) + lambda_init;
        sGG[tid] = gamma[h * HD2 + tid];
        sGB[tid] = beta[h * HD2 + tid];
    }
    __syncthreads();
    const uint32_t tmem = s_tmem;

    bool lead = false;
    if (wid == 0) lead = elect_one();

    const uint32_t IDESC_S = (1u << 4) | (1u << 7) | (1u << 10) | (8u << 17) | (8u << 24);
    const uint32_t IDESC_O = (1u << 4) | (16u << 17) | (8u << 24);
    const int nkt = 2 * qb + 2;
    const int qrow = q0 + row;

    auto tma_K = [&](int kb2, int buf) {
        const uint32_t b = tile_u32 + (buf ? KBUF1 : KBUF0);
        const uint32_t fb = KF[buf];
        const int k0 = kb2 * 64;
        mbar_expect_tx(fb, 32768);
        tma_2d(b,             &tKh, 0,  h * SEQ + k0, fb);
        tma_2d(b + 8 * 1024,  &tKl, 0,  h * SEQ + k0, fb);
        tma_2d(b + 16 * 1024, &tKh, 64, h * SEQ + k0, fb);
        tma_2d(b + 24 * 1024, &tKl, 64, h * SEQ + k0, fb);
    };
    auto tma_V = [&](int kb2, int buf) {
        const uint32_t b = tile_u32 + (buf ? VBUF1 : VBUF0);
        const uint32_t fb = VF[buf];
        const int k0 = kb2 * 64;
        mbar_expect_tx(fb, 32768);
        tma_2d(b,             &tVh, k0, h * 128, fb);
        tma_2d(b + 16 * 1024, &tVl, k0, h * 128, fb);
    };
    auto issue_S = [&](int kb2) {
        const int buf = kb2 & 1;
        const uint32_t kbse = tile_u32 + (buf ? KBUF1 : KBUF0);
#pragma unroll
        for (int st = 0; st < 2; st++) {
            const uint32_t sd = tmem + 256 + st * 64;
            uint64_t dQh = make_desc(tile_u32 + (st ? AQ2H : AQ1H));
            uint64_t dQl = make_desc(tile_u32 + (st ? AQ2L : AQ1L));
            uint64_t dKh = make_desc(kbse + st * 16 * 1024);
            uint64_t dKl = make_desc(kbse + st * 16 * 1024 + 8 * 1024);
#pragma unroll
            for (int ks = 0; ks < 4; ks++) {
                mma_f16_ss(sd, dQh + ks * 2, dKh + ks * 2, IDESC_S, ks != 0);
                mma_f16_ss(sd, dQh + ks * 2, dKl + ks * 2, IDESC_S, 1);
                mma_f16_ss(sd, dQl + ks * 2, dKh + ks * 2, IDESC_S, 1);
            }
        }
        tc_commit(SB);
    };
    auto issue_PV = [&](int kb2) {
        const int buf = kb2 & 1;
        const uint32_t vbse = tile_u32 + (buf ? VBUF1 : VBUF0);
        uint64_t dVh = make_desc(vbse);
        uint64_t dVl = make_desc(vbse + 16 * 1024);
#pragma unroll
        for (int st = 0; st < 2; st++) {
            const uint32_t od = tmem + st * 128;
            const uint32_t ah = tmem + 384 + st * 32;
#pragma unroll
            for (int ks = 0; ks < 4; ks++) {
                mma_f16_ts(od, ah + ks * 8, dVh + ks * 2, IDESC_O,
                           (kb2 != 0) || (ks != 0));
                mma_f16_ts(od, ah + ks * 8, dVl + ks * 2, IDESC_O, 1);
            }
        }
        tc_commit(PVB);
    };

    // ---- prologue ----
    uint32_t phKF[2] = {0, 0}, phVF[2] = {0, 0};
    if (lead) {
        mbar_expect_tx(QB, 65536);
        tma_2d(tile_u32 + AQ1H, &tQh, 0,  h * SEQ + q0, QB);
        tma_2d(tile_u32 + AQ2H, &tQh, 64, h * SEQ + q0, QB);
        tma_2d(tile_u32 + AQ1L, &tQl, 0,  h * SEQ + q0, QB);
        tma_2d(tile_u32 + AQ2L, &tQl, 64, h * SEQ + q0, QB);
        tma_K(0, 0);
        tma_V(0, 0);
        tma_K(1, 1);
        tma_V(1, 1);
        mbar_wait(QB, 0);
        mbar_wait(KF[0], 0); phKF[0] ^= 1;
        issue_S(0);
    }

    float L = 0.0f;
    uint32_t phSB = 0, phPV = 0;
    const uint32_t sld = tmem + 256 + strm * 64 + chalf * 32;
    const uint32_t pst = tmem + 384 + strm * 32 + chalf * 16;

    for (int kb = 0; kb < nkt; kb++) {
        mbar_wait(SB, phSB); phSB ^= 1;
        tc_fence_after();
        if (lead && kb + 2 < nkt) tma_K(kb + 2, kb & 1);

        uint32_t sc[32];
        tc_ld32(sc, sld);
        tc_wait_ld();
        tc_fence_before();
        __syncthreads();                 // S TMEM free

        if (lead && kb + 1 < nkt) {
            const int nb = (kb + 1) & 1;
            mbar_wait(KF[nb], phKF[nb]); phKF[nb] ^= 1;
            tc_fence_after();
            issue_S(kb + 1);
        }

        const int colbase = kb * 64 + chalf * 32;
        const bool needmask = (colbase + 31 > q0 + sub * 32);  // warp-uniform
        uint32_t uh[16];
        {
            const float c1 = 0.180336880111120419f;   // 0.125 * log2(e)
            float ls = 0.0f;
            if (needmask) {
#pragma unroll
                for (int t = 0; t < 16; t++) {
                    float s0 = __uint_as_float(sc[2 * t]);
                    float s1 = __uint_as_float(sc[2 * t + 1]);
                    float p0, p1;
                    asm("ex2.approx.f32 %0, %1;" : "=f"(p0) : "f"(s0 * c1));
                    asm("ex2.approx.f32 %0, %1;" : "=f"(p1) : "f"(s1 * c1));
                    if (colbase + 2 * t > qrow)     p0 = 0.0f;
                    if (colbase + 2 * t + 1 > qrow) p1 = 0.0f;
                    ls += p0 + p1;
                    asm("cvt.rn.f16x2.f32 %0, %1, %2;" : "=r"(uh[t]) : "f"(p1), "f"(p0));
                }
            } else {
#pragma unroll
                for (int t = 0; t < 16; t++) {
                    float s0 = __uint_as_float(sc[2 * t]);
                    float s1 = __uint_as_float(sc[2 * t + 1]);
                    float p0, p1;
                    asm("ex2.approx.f32 %0, %1;" : "=f"(p0) : "f"(s0 * c1));
                    asm("ex2.approx.f32 %0, %1;" : "=f"(p1) : "f"(s1 * c1));
                    ls += p0 + p1;
                    asm("cvt.rn.f16x2.f32 %0, %1, %2;" : "=r"(uh[t]) : "f"(p1), "f"(p0));
                }
            }
            L += ls;
        }

        if (kb >= 1) { mbar_wait(PVB, phPV); phPV ^= 1; }
        tc_fence_after();
        if (lead && kb >= 1 && kb + 1 < nkt) tma_V(kb + 1, (kb + 1) & 1);

        tc_st16(pst, uh);
        tc_wait_st();
        tc_fence_before();
        __syncthreads();

        if (lead) {
            tc_fence_after();
            const int vb = kb & 1;
            mbar_wait(VF[vb], phVF[vb]); phVF[vb] ^= 1;
            issue_PV(kb);
        }
    }
    mbar_wait(PVB, phPV);
    tc_fence_after();

    if (chalf == 0) sL[strm][row] = L;
    __syncthreads();
    if (chalf == 1) sL[strm][row] += L;
    __syncthreads();
    const float invL = 1.0f / sL[strm][row];

    // ---- epilogue: combine streams + fused GroupNorm ----
    float* stag = (float*)(tile + KBUF0);       // 128 x 132 fp32 staging (O2/L2)
    if (strm == 1) {
#pragma unroll
        for (int cb = 0; cb < 2; cb++) {
            uint32_t r[32];
            tc_ld32(r, tmem + 128 + chalf * 64 + cb * 32);
            tc_wait_ld();
            float4* dst = (float4*)&stag[row * 132 + chalf * 64 + cb * 32];
#pragma unroll
            for (int c = 0; c < 32; c += 4)
                dst[c >> 2] = make_float4(__uint_as_float(r[c]) * invL,
                                          __uint_as_float(r[c + 1]) * invL,
                                          __uint_as_float(r[c + 2]) * invL,
                                          __uint_as_float(r[c + 3]) * invL);
        }
    }
    tc_fence_before();
    __syncthreads();

    float val[64];
    if (strm == 0) {
        float s = 0.0f, sq = 0.0f;
#pragma unroll
        for (int cb = 0; cb < 2; cb++) {
            uint32_t r[32];
            tc_ld32(r, tmem + chalf * 64 + cb * 32);
            tc_wait_ld();
#pragma unroll
            for (int c = 0; c < 32; c++) {
                int col = chalf * 64 + cb * 32 + c;
                float v = __uint_as_float(r[c]) * invL
                        - sLAM[col] * stag[row * 132 + col];
                val[cb * 32 + c] = v;
                s += v;
                sq = fmaf(v, v, sq);
            }
        }
        pS[row][chalf] = s;
        pQ[row][chalf] = sq;
    }
    tc_fence_before();
    __syncthreads();
    if (strm == 0) {
        const float mu = (pS[row][0] + pS[row][1]) * (1.0f / 128.0f);
        const float ex2 = (pQ[row][0] + pQ[row][1]) * (1.0f / 128.0f);
        const float rs = rsqrtf(ex2 - mu * mu + 1e-5f);
        const float gsc = 1.0f - lambda_init;

        uint32_t hp[32], lp[32];
#pragma unroll
        for (int t = 0; t < 32; t++) {
            int col = chalf * 64 + 2 * t;
            float f0 = ((val[2*t]   - mu) * rs * sGG[col]   + sGB[col])   * gsc;
            float f1 = ((val[2*t+1] - mu) * rs * sGG[col+1] + sGB[col+1]) * gsc;
            uint32_t hh;
            asm("cvt.rn.bf16x2.f32 %0, %1, %2;" : "=r"(hh) : "f"(f1), "f"(f0));
            float fh0 = __uint_as_float(hh << 16);
            float fh1 = __uint_as_float(hh & 0xffff0000u);
            uint32_t ll;
            asm("cvt.rn.bf16x2.f32 %0, %1, %2;"
                : "=r"(ll) : "f"(f1 - fh1), "f"(f0 - fh0));
            hp[t] = hh; lp[t] = ll;
        }
        size_t base = (size_t)(q0 + row) * DMODEL + h * HD2 + chalf * 64;
        uint4* yh4 = (uint4*)(yh + base);
        uint4* yl4 = (uint4*)(yl + base);
#pragma unroll
        for (int q = 0; q < 8; q++) {
            yh4[q] = make_uint4(hp[4*q], hp[4*q+1], hp[4*q+2], hp[4*q+3]);
            yl4[q] = make_uint4(lp[4*q], lp[4*q+1], lp[4*q+2], lp[4*q+3]);
        }
    }
    tc_fence_before();
    __syncthreads();
    if (wid == 0) tc_dealloc(tmem, 512);

#else  // ------- naive fallback (portable pass only; never selected) -------
    __shared__ float sq_[128], skv[256], sp[128], ssum[2], sres[128];
    float lam = 0.0f, gmm = 1.0f, bta = 0.0f;
    if (tid < 128) {
        lam = expf(lq1[tid] * lk1[tid]) - expf(lq2[tid] * lk2[tid]) + lambda_init;
        gmm = gamma[h * HD2 + tid];
        bta = beta[h * HD2 + tid];
    }
    for (int r = 0; r < 128; r++) {
        const int qrow = q0 + r;
        if (tid < 128) {
            size_t qi = ((size_t)h * SEQ + qrow) * 128 + tid;
            sq_[tid] = __bfloat162float(Qh[qi]) + __bfloat162float(Ql[qi]);
        }
        float o1 = 0, o2 = 0, L1 = 0, L2 = 0;
        for (int k = 0; k <= qrow; k++) {
            __syncthreads();
            if (tid < 128) {
                size_t ki = ((size_t)h * SEQ + k) * 128 + tid;
                sp[tid] = sq_[tid] * (__bfloat162float(Kh[ki]) + __bfloat162float(Kl[ki]));
                size_t vi = ((size_t)h * 128 + tid) * SEQ + k;
                skv[tid] = __half2float(Vth[vi]) + __half2float(Vtl[vi]);
            }
            __syncthreads();
            if (tid == 0) {
                float a = 0, b = 0;
                for (int d = 0; d < 64; d++) { a += sp[d]; b += sp[64 + d]; }
                ssum[0] = a; ssum[1] = b;
            }
            __syncthreads();
            if (tid < 128) {
                float e1 = expf(ssum[0] * 0.125f), e2 = expf(ssum[1] * 0.125f);
                o1 += e1 * skv[tid]; o2 += e2 * skv[tid];
                L1 += e1; L2 += e2;
            }
        }
        __syncthreads();
        if (tid < 128) sres[tid] = o1 / L1 - lam * (o2 / L2);
        __syncthreads();
        if (tid == 0) {
            float s = 0, s2 = 0;
            for (int c = 0; c < 128; c++) { s += sres[c]; s2 += sres[c]*sres[c]; }
            ssum[0] = s / 128.0f;
            ssum[1] = s2 / 128.0f;
        }
        __syncthreads();
        if (tid < 128) {
            float mu = ssum[0];
            float rs = rsqrtf(ssum[1] - mu * mu + 1e-5f);
            float o = ((sres[tid] - mu) * rs * gmm + bta) * (1.0f - lambda_init);
            size_t oi = (size_t)qrow * DMODEL + h * HD2 + tid;
            __nv_bfloat16 hi = __float2bfloat16(o);
            yh[oi] = hi;
            yl[oi] = __float2bfloat16(o - __bfloat162float(hi));
        }
        __syncthreads();
    }
#endif
}

// ---------------------------------------------------------------------------
typedef CUresult (*tmap_encode_fn)(
    CUtensorMap*, CUtensorMapDataType, cuuint32_t, void*,
    const cuuint64_t*, const cuuint64_t*, const cuuint32_t*, const cuuint32_t*,
    CUtensorMapInterleave, CUtensorMapSwizzle, CUtensorMapL2promotion,
    CUtensorMapFloatOOBfill);

static void make_map_2d_t(tmap_encode_fn enc, CUtensorMap* m, void* ptr,
                          CUtensorMapDataType dt,
                          uint64_t inner, uint64_t outer, uint32_t box_outer) {
    cuuint64_t dims[2]    = {inner, outer};
    cuuint64_t strides[1] = {inner * 2};
    cuuint32_t box[2]     = {64u, box_outer};
    cuuint32_t es[2]      = {1u, 1u};
    enc(m, dt, 2, ptr, dims, strides, box, es,
        CU_TENSOR_MAP_INTERLEAVE_NONE, CU_TENSOR_MAP_SWIZZLE_128B,
        CU_TENSOR_MAP_L2_PROMOTION_L2_128B, CU_TENSOR_MAP_FLOAT_OOB_FILL_NONE);
}
static void make_map_2d(tmap_encode_fn enc, CUtensorMap* m, void* ptr,
                        uint64_t inner, uint64_t outer, uint32_t box_outer) {
    make_map_2d_t(enc, m, ptr, CU_TENSOR_MAP_DATA_TYPE_BFLOAT16,
                  inner, outer, box_outer);
}

extern "C" void kernel_launch(void* const* d_in, const int* in_sizes, int n_in,
                              void* d_out, int out_size) {
    const float* x    = (const float*)d_in[0];
    const float* Wqkv = (const float*)d_in[1];
    const float* Wo   = (const float*)d_in[2];
    const float* lq1  = (const float*)d_in[3];
    const float* lk1  = (const float*)d_in[4];
    const float* lq2  = (const float*)d_in[5];
    const float* lk2  = (const float*)d_in[6];
    const float* gg   = (const float*)d_in[7];
    const float* gb   = (const float*)d_in[8];
    float* out = (float*)d_out;

    __nv_bfloat16 *xh, *xl, *wqh, *wql, *woh, *wol, *yh, *yl;
    __nv_bfloat16 *qh, *ql, *kh, *kl;
    __half *vth, *vtl;
    cudaGetSymbolAddress((void**)&xh,  g_xh);  cudaGetSymbolAddress((void**)&xl,  g_xl);
    cudaGetSymbolAddress((void**)&wqh, g_wqh); cudaGetSymbolAddress((void**)&wql, g_wql);
    cudaGetSymbolAddress((void**)&woh, g_woh); cudaGetSymbolAddress((void**)&wol, g_wol);
    cudaGetSymbolAddress((void**)&yh,  g_yh);  cudaGetSymbolAddress((void**)&yl,  g_yl);
    cudaGetSymbolAddress((void**)&qh,  g_qh);  cudaGetSymbolAddress((void**)&ql,  g_ql);
    cudaGetSymbolAddress((void**)&kh,  g_kh);  cudaGetSymbolAddress((void**)&kl,  g_kl);
    cudaGetSymbolAddress((void**)&vth, g_vth); cudaGetSymbolAddress((void**)&vtl, g_vtl);

    tmap_encode_fn enc = nullptr;
    {
        void* p = nullptr;
        cudaDriverEntryPointQueryResult st;
        cudaGetDriverEntryPoint("cuTensorMapEncodeTiled", &p, cudaEnableDefault, &st);
        enc = (tmap_encode_fn)p;
    }

    // B boxes are 128 rows (each cg2 rank loads its own half)
    CUtensorMap mXh, mXl, mWqh, mWql, mYh, mYl, mWoh, mWol;
    make_map_2d(enc, &mXh,  xh,  DMODEL, SEQ,    128);
    make_map_2d(enc, &mXl,  xl,  DMODEL, SEQ,    128);
    make_map_2d(enc, &mWqh, wqh, DMODEL, QKVN,   128);
    make_map_2d(enc, &mWql, wql, DMODEL, QKVN,   128);
    make_map_2d(enc, &mYh,  yh,  DMODEL, SEQ,    128);
    make_map_2d(enc, &mYl,  yl,  DMODEL, SEQ,    128);
    make_map_2d(enc, &mWoh, woh, DMODEL, DMODEL, 128);
    make_map_2d(enc, &mWol, wol, DMODEL, DMODEL, 128);

    CUtensorMap mQh, mQl, mKh, mKl, mVh, mVl;
    make_map_2d(enc, &mQh, qh,  128, (uint64_t)NHEADS * SEQ, 128);
    make_map_2d(enc, &mQl, ql,  128, (uint64_t)NHEADS * SEQ, 128);
    make_map_2d(enc, &mKh, kh,  128, (uint64_t)NHEADS * SEQ, 64);
    make_map_2d(enc, &mKl, kl,  128, (uint64_t)NHEADS * SEQ, 64);
    make_map_2d_t(enc, &mVh, vth, CU_TENSOR_MAP_DATA_TYPE_FLOAT16,
                  SEQ, (uint64_t)NHEADS * 128, 128);
    make_map_2d_t(enc, &mVl, vtl, CU_TENSOR_MAP_DATA_TYPE_FLOAT16,
                  SEQ, (uint64_t)NHEADS * 128, 128);

    cudaFuncSetAttribute(gemm_qkv, cudaFuncAttributeMaxDynamicSharedMemorySize, GEMM_SMEM);
    cudaFuncSetAttribute(gemm_tma, cudaFuncAttributeMaxDynamicSharedMemorySize, GEMM_SMEM);
    cudaFuncSetAttribute(attn_tc, cudaFuncAttributeMaxDynamicSharedMemorySize, ATT_DYN);

    // 0) split GEMM operands
    {
        int n4 = SEQ * DMODEL / 4;
        split_f32<<<(n4 + 255) / 256, 256>>>(x, xh, xl, n4);
        n4 = QKVN * DMODEL / 4;
        split_f32<<<(n4 + 255) / 256, 256>>>(Wqkv, wqh, wql, n4);
        n4 = DMODEL * DMODEL / 4;
        split_f32<<<(n4 + 255) / 256, 256>>>(Wo, woh, wol, n4);
    }

    // 1) qkv GEMM (cg2 pairs along grid.x = M) with fused split epilogue
    gemm_qkv<<<dim3(SEQ / BM, QKVN / BN), 256, GEMM_SMEM>>>(
        mXh, mXl, mWqh, mWql, xh, xl, wqh, wql,
        qh, ql, kh, kl, vth, vtl, DMODEL);

    // 2) tcgen05 differential flash attention + fused GroupNorm -> yh/yl
    attn_tc<<<dim3(SEQ / 128, NHEADS), 512, ATT_DYN>>>(
        mQh, mQl, mKh, mKl, mVh, mVl,
        qh, ql, kh, kl, vth, vtl, lq1, lk1, lq2, lk2, gg, gb, yh, yl);

    // 3) out = y @ W_o^T (cg2 pairs along grid.x = M)
    gemm_tma<<<dim3(SEQ / BM, DMODEL / BN), 256, GEMM_SMEM>>>(
        mYh, mYl, mWoh, mWol, yh, yl, woh, wol, out, DMODEL, DMODEL);
}

// round 15
// speedup vs baseline: 1.0671x; 1.0671x over previous
#include <cuda_runtime.h>
#include <cuda.h>
#include <cuda_bf16.h>
#include <cuda_fp16.h>
#include <math.h>
#include <stdint.h>

#define SEQ     2048
#define DMODEL  2048
#define NHEADS  16
#define HD2     128
#define QKVN    (3*DMODEL)   // 6144
#define QSC     0.180336880111120419f   // 0.125 * log2(e), folded into Q

// tcgen05/TMA exist only in the arch-specific (sm_103a) device pass.
#if !defined(__CUDA_ARCH__) || defined(__CUDA_ARCH_FEAT_SM103_ALL)
#define TC_HELPERS_VISIBLE 1
#endif
#if defined(__CUDA_ARCH__) && defined(__CUDA_ARCH_FEAT_SM103_ALL)
#define TC_RUN 1
#endif

// ---------------- scratch (static device globals; no allocations) ----------
__device__ __nv_bfloat16 g_xh[(size_t)SEQ * DMODEL],  g_xl[(size_t)SEQ * DMODEL];
__device__ __nv_bfloat16 g_wqh[(size_t)QKVN * DMODEL], g_wql[(size_t)QKVN * DMODEL];
__device__ __nv_bfloat16 g_woh[(size_t)DMODEL * DMODEL], g_wol[(size_t)DMODEL * DMODEL];
__device__ __nv_bfloat16 g_yh[(size_t)SEQ * DMODEL],  g_yl[(size_t)SEQ * DMODEL];
__device__ __nv_bfloat16 g_qh[(size_t)NHEADS * SEQ * HD2], g_ql[(size_t)NHEADS * SEQ * HD2];
__device__ __nv_bfloat16 g_kh[(size_t)NHEADS * SEQ * HD2], g_kl[(size_t)NHEADS * SEQ * HD2];
__device__ __half g_vth[(size_t)NHEADS * HD2 * SEQ], g_vtl[(size_t)NHEADS * HD2 * SEQ];

// =============================== PTX helpers ===============================
#ifdef TC_HELPERS_VISIBLE
__device__ __forceinline__ uint32_t smem_u32(const void* p) {
    uint32_t a;
    asm("{ .reg .u64 t; cvta.to.shared.u64 t, %1; cvt.u32.u64 %0, t; }"
        : "=r"(a) : "l"(p));
    return a;
}
__device__ __forceinline__ bool elect_one() {
    uint32_t pred;
    asm volatile("{\n\t.reg .pred p;\n\telect.sync _|p, 0xFFFFFFFF;\n\t"
                 "selp.b32 %0, 1, 0, p;\n\t}" : "=r"(pred));
    return pred != 0;
}
__device__ __forceinline__ uint32_t ctarank() {
    uint32_t r;
    asm("mov.u32 %0, %%cluster_ctarank;" : "=r"(r));
    return r;
}
__device__ __forceinline__ void cluster_sync() {
    asm volatile("barrier.cluster.arrive.aligned;" ::: "memory");
    asm volatile("barrier.cluster.wait.aligned;" ::: "memory");
}
__device__ __forceinline__ void mbar_init(uint32_t a, uint32_t cnt) {
    asm volatile("mbarrier.init.shared.b64 [%0], %1;" :: "r"(a), "r"(cnt) : "memory");
}
__device__ __forceinline__ void mbar_expect_tx(uint32_t a, uint32_t bytes) {
    asm volatile("mbarrier.arrive.expect_tx.shared.b64 _, [%0], %1;"
                 :: "r"(a), "r"(bytes) : "memory");
}
// arrive+expect on the LEADER CTA's barrier (bit24 cleared) from any rank
__device__ __forceinline__ void expect_tx_leader(uint32_t a, uint32_t bytes) {
    asm volatile(
        "{\n\t.reg .b32 lb;\n\tand.b32 lb, %0, 0xFEFFFFFF;\n\t"
        "mbarrier.arrive.expect_tx.shared::cluster.b64 _, [lb], %1;\n\t}"
        :: "r"(a), "r"(bytes) : "memory");
}
__device__ __forceinline__ void mbar_wait(uint32_t a, uint32_t phase) {
    asm volatile(
        "{\n\t.reg .pred P;\n\t"
        "WL_%=:\n\t"
        "mbarrier.try_wait.parity.acquire.cta.shared::cta.b64 P, [%0], %1, 0x989680;\n\t"
        "@P bra WD_%=;\n\t"
        "bra WL_%=;\n\t"
        "WD_%=:\n\t}" :: "r"(a), "r"(phase) : "memory");
}
__device__ __forceinline__ void tma_2d(uint32_t dst, const void* tmap,
                                       int cx, int cy, uint32_t mbar) {
    asm volatile(
        "cp.async.bulk.tensor.2d.shared::cta.global.tile.mbarrier::complete_tx::bytes "
        "[%0], [%1, {%2, %3}], [%4];"
        :: "r"(dst), "l"(tmap), "r"(cx), "r"(cy), "r"(mbar) : "memory");
}
// cg2 TMA: completion tx arrives on the leader CTA's barrier
__device__ __forceinline__ void tma_2d_cg2(uint32_t dst, const void* tmap,
                                           int cx, int cy, uint32_t mbar) {
    asm volatile(
        "{\n\t.reg .b32 lb;\n\tand.b32 lb, %4, 0xFEFFFFFF;\n\t"
        "cp.async.bulk.tensor.2d.cta_group::2.shared::cluster.global.tile"
        ".mbarrier::complete_tx::bytes [%0], [%1, {%2, %3}], [lb];\n\t}"
        :: "r"(dst), "l"(tmap), "r"(cx), "r"(cy), "r"(mbar) : "memory");
}
__device__ __forceinline__ void tc_alloc(uint32_t dst_smem, uint32_t ncols) {
    asm volatile("tcgen05.alloc.cta_group::1.sync.aligned.shared::cta.b32 [%0], %1;"
                 :: "r"(dst_smem), "r"(ncols) : "memory");
}
__device__ __forceinline__ void tc_alloc_cg2(uint32_t dst_smem, uint32_t ncols) {
    asm volatile("tcgen05.alloc.cta_group::2.sync.aligned.shared::cta.b32 [%0], %1;"
                 :: "r"(dst_smem), "r"(ncols) : "memory");
}
__device__ __forceinline__ void tc_relinq() {
    asm volatile("tcgen05.relinquish_alloc_permit.cta_group::1.sync.aligned;");
}
__device__ __forceinline__ void tc_relinq_cg2() {
    asm volatile("tcgen05.relinquish_alloc_permit.cta_group::2.sync.aligned;");
}
__device__ __forceinline__ void tc_dealloc(uint32_t tmem, uint32_t ncols) {
    asm volatile("tcgen05.dealloc.cta_group::1.sync.aligned.b32 %0, %1;"
                 :: "r"(tmem), "r"(ncols));
}
__device__ __forceinline__ void tc_dealloc_cg2(uint32_t tmem, uint32_t ncols) {
    asm volatile("tcgen05.dealloc.cta_group::2.sync.aligned.b32 %0, %1;"
                 :: "r"(tmem), "r"(ncols));
}
__device__ __forceinline__ void tc_commit(uint32_t mbar) {
    asm volatile("tcgen05.commit.cta_group::1.mbarrier::arrive::one.shared::cluster.b64 [%0];"
                 :: "r"(mbar) : "memory");
}
__device__ __forceinline__ void tc_commit_mc2(uint32_t mbar, uint16_t mask) {
    asm volatile(
        "tcgen05.commit.cta_group::2.mbarrier::arrive::one.shared::cluster"
        ".multicast::cluster.b64 [%0], %1;"
        :: "r"(mbar), "h"(mask) : "memory");
}
__device__ __forceinline__ void tc_fence_after() {
    asm volatile("tcgen05.fence::after_thread_sync;" ::: "memory");
}
__device__ __forceinline__ void tc_fence_before() {
    asm volatile("tcgen05.fence::before_thread_sync;" ::: "memory");
}
__device__ __forceinline__ void fence_async_shared() {
    asm volatile("fence.proxy.async.shared::cta;" ::: "memory");
}
__device__ __forceinline__ void tc_wait_ld() {
    asm volatile("tcgen05.wait::ld.sync.aligned;" ::: "memory");
}
__device__ __forceinline__ void tc_wait_st() {
    asm volatile("tcgen05.wait::st.sync.aligned;" ::: "memory");
}
__device__ __forceinline__ void mma_f16_ss(uint32_t d, uint64_t ad, uint64_t bd,
                                           uint32_t idesc, uint32_t en) {
    asm volatile(
        "{\n\t.reg .pred p;\n\tsetp.ne.u32 p, %4, 0;\n\t"
        "tcgen05.mma.cta_group::1.kind::f16 [%0], %1, %2, %3, {%5,%5,%5,%5}, p;\n\t}"
        :: "r"(d), "l"(ad), "l"(bd), "r"(idesc), "r"(en), "r"(0u) : "memory");
}
__device__ __forceinline__ void mma_f16_ss_cg2(uint32_t d, uint64_t ad, uint64_t bd,
                                               uint32_t idesc, uint32_t en) {
    asm volatile(
        "{\n\t.reg .pred p;\n\tsetp.ne.u32 p, %4, 0;\n\t"
        "tcgen05.mma.cta_group::2.kind::f16 [%0], %1, %2, %3, "
        "{%5,%5,%5,%5,%5,%5,%5,%5}, p;\n\t}"
        :: "r"(d), "l"(ad), "l"(bd), "r"(idesc), "r"(en), "r"(0u) : "memory");
}
__device__ __forceinline__ void mma_f16_ts(uint32_t d, uint32_t at, uint64_t bd,
                                           uint32_t idesc, uint32_t en) {
    asm volatile(
        "{\n\t.reg .pred p;\n\tsetp.ne.u32 p, %4, 0;\n\t"
        "tcgen05.mma.cta_group::1.kind::f16 [%0], [%1], %2, %3, {%5,%5,%5,%5}, p;\n\t}"
        :: "r"(d), "r"(at), "l"(bd), "r"(idesc), "r"(en), "r"(0u) : "memory");
}
__device__ __forceinline__ void tc_ld32(uint32_t* r, uint32_t a) {
    asm volatile(
        "tcgen05.ld.sync.aligned.32x32b.x32.b32 "
        "{%0,%1,%2,%3,%4,%5,%6,%7,%8,%9,%10,%11,%12,%13,%14,%15,"
        "%16,%17,%18,%19,%20,%21,%22,%23,%24,%25,%26,%27,%28,%29,%30,%31}, [%32];"
        : "=r"(r[0]),"=r"(r[1]),"=r"(r[2]),"=r"(r[3]),"=r"(r[4]),"=r"(r[5]),"=r"(r[6]),"=r"(r[7]),
          "=r"(r[8]),"=r"(r[9]),"=r"(r[10]),"=r"(r[11]),"=r"(r[12]),"=r"(r[13]),"=r"(r[14]),"=r"(r[15]),
          "=r"(r[16]),"=r"(r[17]),"=r"(r[18]),"=r"(r[19]),"=r"(r[20]),"=r"(r[21]),"=r"(r[22]),"=r"(r[23]),
          "=r"(r[24]),"=r"(r[25]),"=r"(r[26]),"=r"(r[27]),"=r"(r[28]),"=r"(r[29]),"=r"(r[30]),"=r"(r[31])
        : "r"(a));
}
__device__ __forceinline__ void tc_st16(uint32_t a, const uint32_t* r) {
    asm volatile(
        "tcgen05.st.sync.aligned.32x32b.x16.b32 [%0], "
        "{%1,%2,%3,%4,%5,%6,%7,%8,%9,%10,%11,%12,%13,%14,%15,%16};"
        :: "r"(a),
           "r"(r[0]),"r"(r[1]),"r"(r[2]),"r"(r[3]),"r"(r[4]),"r"(r[5]),"r"(r[6]),"r"(r[7]),
           "r"(r[8]),"r"(r[9]),"r"(r[10]),"r"(r[11]),"r"(r[12]),"r"(r[13]),"r"(r[14]),"r"(r[15])
        : "memory");
}
__device__ __forceinline__ uint64_t make_desc(uint32_t addr) {
    const uint64_t base = (2ull << 61) | (1ull << 46) | (64ull << 32) | (1ull << 16); // SW128
    return base | ((addr >> 4) & 0x3FFF);
}
#endif // TC_HELPERS_VISIBLE

// ============ fused split fp32 -> bf16 hi/lo (x, Wqkv, Wo in one) ==========
__global__ void split_all(const float* __restrict__ x,
                          const float* __restrict__ wq,
                          const float* __restrict__ wo,
                          __nv_bfloat16* __restrict__ xh, __nv_bfloat16* __restrict__ xl,
                          __nv_bfloat16* __restrict__ wqh, __nv_bfloat16* __restrict__ wql,
                          __nv_bfloat16* __restrict__ woh, __nv_bfloat16* __restrict__ wol) {
    const int N1 = SEQ * DMODEL / 4;
    const int N2 = N1 + QKVN * DMODEL / 4;
    const int N3 = N2 + DMODEL * DMODEL / 4;
    int i = blockIdx.x * blockDim.x + threadIdx.x;
    if (i >= N3) return;
    const float* in; __nv_bfloat16 *hi, *lo; int j;
    if (i < N1)      { in = x;  hi = xh;  lo = xl;  j = i; }
    else if (i < N2) { in = wq; hi = wqh; lo = wql; j = i - N1; }
    else             { in = wo; hi = woh; lo = wol; j = i - N2; }

    float4 v = ((const float4*)in)[j];
    float f[4] = {v.x, v.y, v.z, v.w};
    union { __nv_bfloat16 b[4]; uint2 u; } H, L;
#pragma unroll
    for (int t = 0; t < 4; t++) {
        H.b[t] = __float2bfloat16(f[t]);
        L.b[t] = __float2bfloat16(f[t] - __bfloat162float(H.b[t]));
    }
    ((uint2*)hi)[j] = H.u;
    ((uint2*)lo)[j] = L.u;
}

// ============ GEMM (cg2 pair: M=256 x N=256, per-CTA 128 rows) =============
#define BM 128
#define BN 256
#define BKE 64
#define STAGE_BYTES (64*1024)
#define OFF_AH 0
#define OFF_AL (16*1024)
#define OFF_BH (32*1024)
#define OFF_BL (48*1024)
#define NSTG 3
#define GEMM_SMEM (NSTG*STAGE_BYTES + 1024)

#ifdef TC_RUN
// 3-stage cg2 mainloop; executed by warp 0 of both CTAs in the pair (R13 form).
__device__ __forceinline__ void gemm_mainloop_cg2(
        const CUtensorMap* tAh, const CUtensorMap* tAl,
        const CUtensorMap* tBh, const CUtensorMap* tBl,
        uint32_t tile_u32, const uint32_t* F, const uint32_t* E,
        uint32_t tmem, int bm, int bnme, int K, uint32_t rank, bool leader) {
    const uint32_t IDESC = (1u << 4) | (1u << 7) | (1u << 10)
                         | ((BN / 8) << 17) | ((256 / 16) << 24);   // M=256 cg2
    const int NS = K / BKE;
    uint32_t phF[NSTG] = {0, 0, 0}, phE[NSTG] = {0, 0, 0};

    auto tma_stage = [&](int s, int b) {
        const uint32_t base = tile_u32 + (uint32_t)b * STAGE_BYTES;
        const int k0 = s * BKE;
        expect_tx_leader(F[b], 65536);
        tma_2d_cg2(base + OFF_AH, tAh, k0, bm,   F[b]);
        tma_2d_cg2(base + OFF_AL, tAl, k0, bm,   F[b]);
        tma_2d_cg2(base + OFF_BH, tBh, k0, bnme, F[b]);
        tma_2d_cg2(base + OFF_BL, tBl, k0, bnme, F[b]);
    };

    if (!leader) return;

#pragma unroll
    for (int s = 0; s < NSTG; s++)
        if (s < NS) tma_stage(s, s);

    for (int s = 0; s < NS; s++) {
        const int b = s % NSTG;
        if (rank == 0) {
            mbar_wait(F[b], phF[b]); phF[b] ^= 1;
            const uint32_t bb = tile_u32 + (uint32_t)b * STAGE_BYTES;
            uint64_t dAh = make_desc(bb + OFF_AH);
            uint64_t dAl = make_desc(bb + OFF_AL);
            uint64_t dBh = make_desc(bb + OFF_BH);
            uint64_t dBl = make_desc(bb + OFF_BL);
#pragma unroll
            for (int ks = 0; ks < 4; ks++) {
                mma_f16_ss_cg2(tmem, dAh + ks * 2, dBh + ks * 2, IDESC,
                               (s != 0) || (ks != 0));
                mma_f16_ss_cg2(tmem, dAh + ks * 2, dBl + ks * 2, IDESC, 1);
                mma_f16_ss_cg2(tmem, dAl + ks * 2, dBh + ks * 2, IDESC, 1);
            }
            tc_commit_mc2(E[b], 0x3);
        }
        if (s >= 1 && s + 2 < NS) {
            const int pb = (s + 2) % NSTG;
            mbar_wait(E[pb], phE[pb]); phE[pb] ^= 1;
            tma_stage(s + 2, pb);
        }
    }
    const int lb = (NS - 1) % NSTG;
    mbar_wait(E[lb], phE[lb]);
}
#endif

// fp32 register-tiled fallback core (portable pass only)
template <typename EPI>
__device__ __forceinline__ void gemm_fallback(
        char* smem, int tid, int bm, int bn, int K,
        const __nv_bfloat16* Ah, const __nv_bfloat16* Al,
        const __nv_bfloat16* Bh, const __nv_bfloat16* Bl, EPI epi) {
    float* As = (float*)smem;
    float* Bs = As + 16 * 132;
    const int tx   = tid & 15;
    const int ty   = tid >> 4;
    const int lrow = tid >> 2;
    const int lcol = (tid & 3) << 2;

    for (int nh = 0; nh < 2; nh++) {
        const int bnn = bn + nh * 128;
        float acc[8][8];
#pragma unroll
        for (int i = 0; i < 8; i++)
#pragma unroll
            for (int j = 0; j < 8; j++) acc[i][j] = 0.0f;

        for (int k0 = 0; k0 < K; k0 += 16) {
            __syncthreads();
#pragma unroll
            for (int r = 0; r < 2; r++) {
                const int row = lrow + r * 64;
                const size_t ao = (size_t)(bm + row) * K + k0 + lcol;
                const size_t bo = (size_t)(bnn + row) * K + k0 + lcol;
                uint2 uah = *(const uint2*)(Ah + ao), ual = *(const uint2*)(Al + ao);
                uint2 ubh = *(const uint2*)(Bh + bo), ubl = *(const uint2*)(Bl + bo);
                const __nv_bfloat16* ah4 = (const __nv_bfloat16*)&uah;
                const __nv_bfloat16* al4 = (const __nv_bfloat16*)&ual;
                const __nv_bfloat16* bh4 = (const __nv_bfloat16*)&ubh;
                const __nv_bfloat16* bl4 = (const __nv_bfloat16*)&ubl;
#pragma unroll
                for (int j = 0; j < 4; j++) {
                    As[(lcol + j) * 132 + row] =
                        __bfloat162float(ah4[j]) + __bfloat162float(al4[j]);
                    Bs[(lcol + j) * 132 + row] =
                        __bfloat162float(bh4[j]) + __bfloat162float(bl4[j]);
                }
            }
            __syncthreads();

#pragma unroll
            for (int k = 0; k < 16; k++) {
                float4 a0 = *(const float4*)&As[k * 132 + ty * 8];
                float4 a1 = *(const float4*)&As[k * 132 + ty * 8 + 4];
                float4 b0 = *(const float4*)&Bs[k * 132 + tx * 8];
                float4 b1 = *(const float4*)&Bs[k * 132 + tx * 8 + 4];
                float av[8] = {a0.x, a0.y, a0.z, a0.w, a1.x, a1.y, a1.z, a1.w};
                float bv[8] = {b0.x, b0.y, b0.z, b0.w, b1.x, b1.y, b1.z, b1.w};
#pragma unroll
                for (int i = 0; i < 8; i++)
#pragma unroll
                    for (int j = 0; j < 8; j++)
                        acc[i][j] = fmaf(av[i], bv[j], acc[i][j]);
            }
        }
        __syncthreads();
#pragma unroll
        for (int i = 0; i < 8; i++)
#pragma unroll
            for (int j = 0; j < 8; j++)
                epi(bm + ty * 8 + i, bnn + tx * 8 + j, acc[i][j]);
    }
}

// ===== GEMM 1: qkv = x @ Wqkv^T (cg2), epilogue splits into q/k/vT =========
// Q is pre-scaled by QSC so attention scores arrive ready for ex2.
__global__ __launch_bounds__(256, 1) __cluster_dims__(2, 1, 1)
void gemm_qkv(const __grid_constant__ CUtensorMap tAh,
              const __grid_constant__ CUtensorMap tAl,
              const __grid_constant__ CUtensorMap tBh,
              const __grid_constant__ CUtensorMap tBl,
              const __nv_bfloat16* __restrict__ Ah,
              const __nv_bfloat16* __restrict__ Al,
              const __nv_bfloat16* __restrict__ Bh,
              const __nv_bfloat16* __restrict__ Bl,
              __nv_bfloat16* __restrict__ qh, __nv_bfloat16* __restrict__ ql,
              __nv_bfloat16* __restrict__ kh, __nv_bfloat16* __restrict__ kl,
              __half* __restrict__ vth, __half* __restrict__ vtl, int K) {
    extern __shared__ __align__(16) char smem[];
    const int tid = threadIdx.x;
    const int bm = blockIdx.x * BM;          // M along x (cluster pairs)
    const int bn = blockIdx.y * BN;          // N along y

#ifdef TC_RUN
    __shared__ uint32_t s_tmem;
    __shared__ __align__(8) unsigned long long s_mbar[2 * NSTG];

    const int wid = tid >> 5;
    const int lane = tid & 31;
    const uint32_t rank = ctarank();

    const uint32_t smem_base = smem_u32(smem);
    const uint32_t tile_u32  = (smem_base + 1023) & ~1023u;
    const uint32_t mb = smem_u32(&s_mbar[0]);
    uint32_t F[NSTG] = {mb, mb + 8, mb + 16};
    uint32_t E[NSTG] = {mb + 24, mb + 32, mb + 40};

    if (wid == 0) { tc_alloc_cg2(smem_u32(&s_tmem), 256); tc_relinq_cg2(); }
    if (tid == 0) {
#pragma unroll
        for (int i = 0; i < NSTG; i++) { mbar_init(F[i], 2); mbar_init(E[i], 1); }
        fence_async_shared();
    }
    __syncthreads();
    cluster_sync();
    const uint32_t tmem = s_tmem;

    if (wid == 0)
        gemm_mainloop_cg2(&tAh, &tAl, &tBh, &tBl, tile_u32, F, E,
                          tmem, bm, bn + (int)rank * 128, K, rank, elect_one());
    __syncthreads();
    tc_fence_after();

    // epilogue: each 128-col half = one head of one of q/k/v (own 128 rows)
    {
        const int g = wid >> 2;
        const int sub = wid & 3;
        const int srow = bm + sub * 32 + lane;
        const int gcolb = bn + g * 128;
        const int region = gcolb >> 11;          // 0=q, 1=k, 2=v
        const int head = (gcolb & 2047) >> 7;
        const float qsc = (region == 0) ? QSC : 1.0f;

#pragma unroll
        for (int cb = 0; cb < 4; cb++) {
            uint32_t r[32];
            tc_ld32(r, tmem + g * 128 + cb * 32);
            tc_wait_ld();

            if (region < 2) {
                __nv_bfloat16* dh = region ? kh : qh;
                __nv_bfloat16* dl = region ? kl : ql;
                uint32_t hp[16], lp[16];
#pragma unroll
                for (int t = 0; t < 16; t++) {
                    float f0 = __uint_as_float(r[2 * t]) * qsc;
                    float f1 = __uint_as_float(r[2 * t + 1]) * qsc;
                    uint32_t h;
                    asm("cvt.rn.bf16x2.f32 %0, %1, %2;" : "=r"(h) : "f"(f1), "f"(f0));
                    float fh0 = __uint_as_float(h << 16);
                    float fh1 = __uint_as_float(h & 0xffff0000u);
                    uint32_t l;
                    asm("cvt.rn.bf16x2.f32 %0, %1, %2;"
                        : "=r"(l) : "f"(f1 - fh1), "f"(f0 - fh0));
                    hp[t] = h; lp[t] = l;
                }
                size_t base = ((size_t)head * SEQ + srow) * 128 + cb * 32;
                uint4* dh4 = (uint4*)(dh + base);
                uint4* dl4 = (uint4*)(dl + base);
#pragma unroll
                for (int q = 0; q < 4; q++) {
                    dh4[q] = make_uint4(hp[4*q], hp[4*q+1], hp[4*q+2], hp[4*q+3]);
                    dl4[q] = make_uint4(lp[4*q], lp[4*q+1], lp[4*q+2], lp[4*q+3]);
                }
            } else {
#pragma unroll
                for (int c = 0; c < 32; c++) {
                    float f = __uint_as_float(r[c]);
                    __half hi = __float2half_rn(f);
                    __half lo = __float2half_rn(f - __half2float(hi));
                    size_t idx = ((size_t)head * 128 + cb * 32 + c) * SEQ + srow;
                    vth[idx] = hi;
                    vtl[idx] = lo;
                }
            }
        }
    }
    tc_fence_before();
    __syncthreads();
    if (wid == 0) tc_dealloc_cg2(tmem, 256);
    cluster_sync();

#else
    gemm_fallback(smem, tid, bm, bn, K, Ah, Al, Bh, Bl,
        [&](int row, int gcol, float f) {
            int region = gcol >> 11;
            int head = (gcol & 2047) >> 7;
            int c = gcol & 127;
            if (region < 2) {
                if (region == 0) f *= QSC;
                __nv_bfloat16* dh = region ? kh : qh;
                __nv_bfloat16* dl = region ? kl : ql;
                size_t o = ((size_t)head * SEQ + row) * 128 + c;
                __nv_bfloat16 hi = __float2bfloat16(f);
                dh[o] = hi;
                dl[o] = __float2bfloat16(f - __bfloat162float(hi));
            } else {
                size_t o = ((size_t)head * 128 + c) * SEQ + row;
                __half hi = __float2half_rn(f);
                vth[o] = hi;
                vtl[o] = __float2half_rn(f - __half2float(hi));
            }
        });
#endif
}

// ============== GEMM 2: out = y @ Wo^T (cg2), fp32 epilogue ================
__global__ __launch_bounds__(256, 1) __cluster_dims__(2, 1, 1)
void gemm_tma(const __grid_constant__ CUtensorMap tAh,
              const __grid_constant__ CUtensorMap tAl,
              const __grid_constant__ CUtensorMap tBh,
              const __grid_constant__ CUtensorMap tBl,
              const __nv_bfloat16* __restrict__ Ah,
              const __nv_bfloat16* __restrict__ Al,
              const __nv_bfloat16* __restrict__ Bh,
              const __nv_bfloat16* __restrict__ Bl,
              float* __restrict__ C, int N, int K) {
    extern __shared__ __align__(16) char smem[];
    const int tid = threadIdx.x;
    const int bm = blockIdx.x * BM;
    const int bn = blockIdx.y * BN;

#ifdef TC_RUN
    __shared__ uint32_t s_tmem;
    __shared__ __align__(8) unsigned long long s_mbar[2 * NSTG];

    const int wid = tid >> 5;
    const int lane = tid & 31;
    const uint32_t rank = ctarank();

    const uint32_t smem_base = smem_u32(smem);
    const uint32_t tile_u32  = (smem_base + 1023) & ~1023u;
    const uint32_t mb = smem_u32(&s_mbar[0]);
    uint32_t F[NSTG] = {mb, mb + 8, mb + 16};
    uint32_t E[NSTG] = {mb + 24, mb + 32, mb + 40};

    if (wid == 0) { tc_alloc_cg2(smem_u32(&s_tmem), 256); tc_relinq_cg2(); }
    if (tid == 0) {
#pragma unroll
        for (int i = 0; i < NSTG; i++) { mbar_init(F[i], 2); mbar_init(E[i], 1); }
        fence_async_shared();
    }
    __syncthreads();
    cluster_sync();
    const uint32_t tmem = s_tmem;

    if (wid == 0)
        gemm_mainloop_cg2(&tAh, &tAl, &tBh, &tBl, tile_u32, F, E,
                          tmem, bm, bn + (int)rank * 128, K, rank, elect_one());
    __syncthreads();
    tc_fence_after();

    {
        const int g = wid >> 2;
        const int sub = wid & 3;
        float* crow = C + (size_t)(bm + sub * 32 + lane) * N + bn + g * 128;
#pragma unroll
        for (int cb = 0; cb < 4; cb++) {
            uint32_t r[32];
            tc_ld32(r, tmem + g * 128 + cb * 32);
            tc_wait_ld();
#pragma unroll
            for (int c = 0; c < 32; c += 4) {
                float4 o = make_float4(__uint_as_float(r[c]), __uint_as_float(r[c + 1]),
                                       __uint_as_float(r[c + 2]), __uint_as_float(r[c + 3]));
                *(float4*)(crow + cb * 32 + c) = o;
            }
        }
    }
    tc_fence_before();
    __syncthreads();
    if (wid == 0) tc_dealloc_cg2(tmem, 256);
    cluster_sync();

#else
    gemm_fallback(smem, tid, bm, bn, K, Ah, Al, Bh, Bl,
        [&](int row, int gcol, float f) {
            C[(size_t)row * N + gcol] = f;
        });
#endif
}

// ============ tcgen05 differential flash attention + fused GN ==============
#define AQ1H 0
#define AQ1L (16*1024)
#define AQ2H (32*1024)
#define AQ2L (48*1024)
#define KBUF0 (64*1024)
#define KBUF1 (96*1024)
#define VBUF0 (128*1024)
#define VBUF1 (160*1024)
#define ATT_DYN (193*1024)
// TMEM cols: O1 0-127 | O2 128-255 | S1 256-319 | S2 320-383
//            P1 384-415 | P2 416-447   (P in fp16)

__global__ __launch_bounds__(512, 1)
void attn_tc(const __grid_constant__ CUtensorMap tQh,
             const __grid_constant__ CUtensorMap tQl,
             const __grid_constant__ CUtensorMap tKh,
             const __grid_constant__ CUtensorMap tKl,
             const __grid_constant__ CUtensorMap tVh,
             const __grid_constant__ CUtensorMap tVl,
             const __nv_bfloat16* __restrict__ Qh, const __nv_bfloat16* __restrict__ Ql,
             const __nv_bfloat16* __restrict__ Kh, const __nv_bfloat16* __restrict__ Kl,
             const __half* __restrict__ Vth, const __half* __restrict__ Vtl,
             const float* __restrict__ lq1, const float* __restrict__ lk1,
             const float* __restrict__ lq2, const float* __restrict__ lk2,
             const float* __restrict__ gamma, const float* __restrict__ beta,
             __nv_bfloat16* __restrict__ yh, __nv_bfloat16* __restrict__ yl) {
    extern __shared__ __align__(16) char smem[];
    const int tid = threadIdx.x;
    const int h = blockIdx.y;
    const int qb = gridDim.x - 1 - blockIdx.x;
    const int q0 = qb * 128;
    const float lambda_init = 0.8f - 0.6f * expf(-0.3f * 12.0f);

#ifdef TC_RUN
    __shared__ uint32_t s_tmem;
    __shared__ __align__(8) unsigned long long s_mbar[7];
    __shared__ float sLAM[128], sGG[128], sGB[128];
    __shared__ float sL[2][128];
    __shared__ float pS[128][2], pQ[128][2];

    const int wid = tid >> 5;
    const int lane = tid & 31;
    const int sub   = wid & 3;
    const int strm  = (wid >> 2) & 1;
    const int chalf = (wid >> 3) & 1;
    const int row = sub * 32 + lane;

    const uint32_t smem_base = smem_u32(smem);
    const uint32_t tile_u32  = (smem_base + 1023) & ~1023u;
    char* tile = smem + (tile_u32 - smem_base);
    const uint32_t QB  = smem_u32(&s_mbar[0]);
    const uint32_t SB  = QB + 8;
    const uint32_t PVB = QB + 16;
    const uint32_t KF[2] = {QB + 24, QB + 32};
    const uint32_t VF[2] = {QB + 40, QB + 48};

    if (wid == 0) { tc_alloc(smem_u32(&s_tmem), 512); tc_relinq(); }
    if (tid == 0) {
        mbar_init(QB, 1); mbar_init(SB, 1); mbar_init(PVB, 1);
        mbar_init(KF[0], 1); mbar_init(KF[1], 1);
        mbar_init(VF[0], 1); mbar_init(VF[1], 1);
        fence_async_shared();
    }
    if (tid < 128) {
        sLAM[tid] = expf(lq1[tid] * lk1[tid]) - expf(lq2[tid] * lk2[tid]) + lambda_init;
        sGG[tid] = gamma[h * HD2 + tid];
        sGB[tid] = beta[h * HD2 + tid];
    }
    __syncthreads();
    const uint32_t tmem = s_tmem;

    bool lead = false;
    if (wid == 0) lead = elect_one();

    const uint32_t IDESC_S = (1u << 4) | (1u << 7) | (1u << 10) | (8u << 17) | (8u << 24);
    const uint32_t IDESC_O = (1u << 4) | (16u << 17) | (8u << 24);
    const int nkt = 2 * qb + 2;
    const int qrow = q0 + row;

    auto tma_K = [&](int kb2, int buf) {
        const uint32_t b = tile_u32 + (buf ? KBUF1 : KBUF0);
        const uint32_t fb = KF[buf];
        const int k0 = kb2 * 64;
        mbar_expect_tx(fb, 32768);
        tma_2d(b,             &tKh, 0,  h * SEQ + k0, fb);
        tma_2d(b + 8 * 1024,  &tKl, 0,  h * SEQ + k0, fb);
        tma_2d(b + 16 * 1024, &tKh, 64, h * SEQ + k0, fb);
        tma_2d(b + 24 * 1024, &tKl, 64, h * SEQ + k0, fb);
    };
    auto tma_V = [&](int kb2, int buf) {
        const uint32_t b = tile_u32 + (buf ? VBUF1 : VBUF0);
        const uint32_t fb = VF[buf];
        const int k0 = kb2 * 64;
        mbar_expect_tx(fb, 32768);
        tma_2d(b,             &tVh, k0, h * 128, fb);
        tma_2d(b + 16 * 1024, &tVl, k0, h * 128, fb);
    };
    auto issue_S = [&](int kb2) {
        const int buf = kb2 & 1;
        const uint32_t kbse = tile_u32 + (buf ? KBUF1 : KBUF0);
#pragma unroll
        for (int st = 0; st < 2; st++) {
            const uint32_t sd = tmem + 256 + st * 64;
            uint64_t dQh = make_desc(tile_u32 + (st ? AQ2H : AQ1H));
            uint64_t dQl = make_desc(tile_u32 + (st ? AQ2L : AQ1L));
            uint64_t dKh = make_desc(kbse + st * 16 * 1024);
            uint64_t dKl = make_desc(kbse + st * 16 * 1024 + 8 * 1024);
#pragma unroll
            for (int ks = 0; ks < 4; ks++) {
                mma_f16_ss(sd, dQh + ks * 2, dKh + ks * 2, IDESC_S, ks != 0);
                mma_f16_ss(sd, dQh + ks * 2, dKl + ks * 2, IDESC_S, 1);
                mma_f16_ss(sd, dQl + ks * 2, dKh + ks * 2, IDESC_S, 1);
            }
        }
        tc_commit(SB);
    };
    auto issue_PV = [&](int kb2) {
        const int buf = kb2 & 1;
        const uint32_t vbse = tile_u32 + (buf ? VBUF1 : VBUF0);
        uint64_t dVh = make_desc(vbse);
        uint64_t dVl = make_desc(vbse + 16 * 1024);
#pragma unroll
        for (int st = 0; st < 2; st++) {
            const uint32_t od = tmem + st * 128;
            const uint32_t ah = tmem + 384 + st * 32;
#pragma unroll
            for (int ks = 0; ks < 4; ks++) {
                mma_f16_ts(od, ah + ks * 8, dVh + ks * 2, IDESC_O,
                           (kb2 != 0) || (ks != 0));
                mma_f16_ts(od, ah + ks * 8, dVl + ks * 2, IDESC_O, 1);
            }
        }
        tc_commit(PVB);
    };

    // ---- prologue ----
    uint32_t phKF[2] = {0, 0}, phVF[2] = {0, 0};
    if (lead) {
        mbar_expect_tx(QB, 65536);
        tma_2d(tile_u32 + AQ1H, &tQh, 0,  h * SEQ + q0, QB);
        tma_2d(tile_u32 + AQ2H, &tQh, 64, h * SEQ + q0, QB);
        tma_2d(tile_u32 + AQ1L, &tQl, 0,  h * SEQ + q0, QB);
        tma_2d(tile_u32 + AQ2L, &tQl, 64, h * SEQ + q0, QB);
        tma_K(0, 0);
        tma_V(0, 0);
        tma_K(1, 1);
        tma_V(1, 1);
        mbar_wait(QB, 0);
        mbar_wait(KF[0], 0); phKF[0] ^= 1;
        issue_S(0);
    }

    float L = 0.0f;
    uint32_t phSB = 0, phPV = 0;
    const uint32_t sld = tmem + 256 + strm * 64 + chalf * 32;
    const uint32_t pst = tmem + 384 + strm * 32 + chalf * 16;

    for (int kb = 0; kb < nkt; kb++) {
        mbar_wait(SB, phSB); phSB ^= 1;
        tc_fence_after();
        if (lead && kb + 2 < nkt) tma_K(kb + 2, kb & 1);

        uint32_t sc[32];
        tc_ld32(sc, sld);
        tc_wait_ld();
        tc_fence_before();
        __syncthreads();                 // S TMEM free

        if (lead && kb + 1 < nkt) {
            const int nb = (kb + 1) & 1;
            mbar_wait(KF[nb], phKF[nb]); phKF[nb] ^= 1;
            tc_fence_after();
            issue_S(kb + 1);
        }

        // softmax: scores pre-scaled (Q folded 0.125*log2e); fp16x2 ex2 path
        const int colbase = kb * 64 + chalf * 32;
        const bool needmask = (colbase + 31 > q0 + sub * 32);  // warp-uniform
        uint32_t uh[16];
        {
            uint32_t aa[4] = {0, 0, 0, 0};
            if (needmask) {
#pragma unroll
                for (int t = 0; t < 16; t++) {
                    uint32_t hs, p;
                    asm("cvt.rn.f16x2.f32 %0, %1, %2;" : "=r"(hs)
                        : "f"(__uint_as_float(sc[2*t+1])), "f"(__uint_as_float(sc[2*t])));
                    asm("ex2.approx.f16x2 %0, %1;" : "=r"(p) : "r"(hs));
                    uint32_t m = 0;
                    if (colbase + 2 * t     <= qrow) m |= 0x0000FFFFu;
                    if (colbase + 2 * t + 1 <= qrow) m |= 0xFFFF0000u;
                    p &= m;
                    uh[t] = p;
                    asm("add.rn.f16x2 %0, %0, %1;" : "+r"(aa[t & 3]) : "r"(p));
                }
            } else {
#pragma unroll
                for (int t = 0; t < 16; t++) {
                    uint32_t hs, p;
                    asm("cvt.rn.f16x2.f32 %0, %1, %2;" : "=r"(hs)
                        : "f"(__uint_as_float(sc[2*t+1])), "f"(__uint_as_float(sc[2*t])));
                    asm("ex2.approx.f16x2 %0, %1;" : "=r"(p) : "r"(hs));
                    uh[t] = p;
                    asm("add.rn.f16x2 %0, %0, %1;" : "+r"(aa[t & 3]) : "r"(p));
                }
            }
            asm("add.rn.f16x2 %0, %0, %1;" : "+r"(aa[0]) : "r"(aa[1]));
            asm("add.rn.f16x2 %0, %0, %1;" : "+r"(aa[2]) : "r"(aa[3]));
            __half2 h2a = *reinterpret_cast<__half2*>(&aa[0]);
            __half2 h2b = *reinterpret_cast<__half2*>(&aa[2]);
            float2 fa = __half22float2(h2a);
            float2 fb = __half22float2(h2b);
            L += (fa.x + fa.y) + (fb.x + fb.y);
        }

        if (kb >= 1) { mbar_wait(PVB, phPV); phPV ^= 1; }
        tc_fence_after();
        if (lead && kb >= 1 && kb + 1 < nkt) tma_V(kb + 1, (kb + 1) & 1);

        tc_st16(pst, uh);
        tc_wait_st();
        tc_fence_before();
        __syncthreads();

        if (lead) {
            tc_fence_after();
            const int vb = kb & 1;
            mbar_wait(VF[vb], phVF[vb]); phVF[vb] ^= 1;
            issue_PV(kb);
        }
    }
    mbar_wait(PVB, phPV);
    tc_fence_after();

    if (chalf == 0) sL[strm][row] = L;
    __syncthreads();
    if (chalf == 1) sL[strm][row] += L;
    __syncthreads();
    const float invL = 1.0f / sL[strm][row];

    // ---- epilogue: combine streams + fused GroupNorm ----
    float* stag = (float*)(tile + KBUF0);       // 128 x 132 fp32 staging (O2/L2)
    if (strm == 1) {
#pragma unroll
        for (int cb = 0; cb < 2; cb++) {
            uint32_t r[32];
            tc_ld32(r, tmem + 128 + chalf * 64 + cb * 32);
            tc_wait_ld();
            float4* dst = (float4*)&stag[row * 132 + chalf * 64 + cb * 32];
#pragma unroll
            for (int c = 0; c < 32; c += 4)
                dst[c >> 2] = make_float4(__uint_as_float(r[c]) * invL,
                                          __uint_as_float(r[c + 1]) * invL,
                                          __uint_as_float(r[c + 2]) * invL,
                                          __uint_as_float(r[c + 3]) * invL);
        }
    }
    tc_fence_before();
    __syncthreads();

    float val[64];
    if (strm == 0) {
        float s = 0.0f, sq = 0.0f;
#pragma unroll
        for (int cb = 0; cb < 2; cb++) {
            uint32_t r[32];
            tc_ld32(r, tmem + chalf * 64 + cb * 32);
            tc_wait_ld();
#pragma unroll
            for (int c = 0; c < 32; c++) {
                int col = chalf * 64 + cb * 32 + c;
                float v = __uint_as_float(r[c]) * invL
                        - sLAM[col] * stag[row * 132 + col];
                val[cb * 32 + c] = v;
                s += v;
                sq = fmaf(v, v, sq);
            }
        }
        pS[row][chalf] = s;
        pQ[row][chalf] = sq;
    }
    tc_fence_before();
    __syncthreads();
    if (strm == 0) {
        const float mu = (pS[row][0] + pS[row][1]) * (1.0f / 128.0f);
        const float ex2 = (pQ[row][0] + pQ[row][1]) * (1.0f / 128.0f);
        const float rs = rsqrtf(ex2 - mu * mu + 1e-5f);
        const float gsc = 1.0f - lambda_init;

        uint32_t hp[32], lp[32];
#pragma unroll
        for (int t = 0; t < 32; t++) {
            int col = chalf * 64 + 2 * t;
            float f0 = ((val[2*t]   - mu) * rs * sGG[col]   + sGB[col])   * gsc;
            float f1 = ((val[2*t+1] - mu) * rs * sGG[col+1] + sGB[col+1]) * gsc;
            uint32_t hh;
            asm("cvt.rn.bf16x2.f32 %0, %1, %2;" : "=r"(hh) : "f"(f1), "f"(f0));
            float fh0 = __uint_as_float(hh << 16);
            float fh1 = __uint_as_float(hh & 0xffff0000u);
            uint32_t ll;
            asm("cvt.rn.bf16x2.f32 %0, %1, %2;"
                : "=r"(ll) : "f"(f1 - fh1), "f"(f0 - fh0));
            hp[t] = hh; lp[t] = ll;
        }
        size_t base = (size_t)(q0 + row) * DMODEL + h * HD2 + chalf * 64;
        uint4* yh4 = (uint4*)(yh + base);
        uint4* yl4 = (uint4*)(yl + base);
#pragma unroll
        for (int q = 0; q < 8; q++) {
            yh4[q] = make_uint4(hp[4*q], hp[4*q+1], hp[4*q+2], hp[4*q+3]);
            yl4[q] = make_uint4(lp[4*q], lp[4*q+1], lp[4*q+2], lp[4*q+3]);
        }
    }
    tc_fence_before();
    __syncthreads();
    if (wid == 0) tc_dealloc(tmem, 512);

#else  // ------- naive fallback (portable pass only; never selected) -------
    __shared__ float sq_[128], skv[256], sp[128], ssum[2], sres[128];
    float lam = 0.0f, gmm = 1.0f, bta = 0.0f;
    if (tid < 128) {
        lam = expf(lq1[tid] * lk1[tid]) - expf(lq2[tid] * lk2[tid]) + lambda_init;
        gmm = gamma[h * HD2 + tid];
        bta = beta[h * HD2 + tid];
    }
    for (int r = 0; r < 128; r++) {
        const int qrow = q0 + r;
        if (tid < 128) {
            size_t qi = ((size_t)h * SEQ + qrow) * 128 + tid;
            sq_[tid] = __bfloat162float(Qh[qi]) + __bfloat162float(Ql[qi]);
        }
        float o1 = 0, o2 = 0, L1 = 0, L2 = 0;
        for (int k = 0; k <= qrow; k++) {
            __syncthreads();
            if (tid < 128) {
                size_t ki = ((size_t)h * SEQ + k) * 128 + tid;
                sp[tid] = sq_[tid] * (__bfloat162float(Kh[ki]) + __bfloat162float(Kl[ki]));
                size_t vi = ((size_t)h * 128 + tid) * SEQ + k;
                skv[tid] = __half2float(Vth[vi]) + __half2float(Vtl[vi]);
            }
            __syncthreads();
            if (tid == 0) {
                float a = 0, b = 0;
                for (int d = 0; d < 64; d++) { a += sp[d]; b += sp[64 + d]; }
                ssum[0] = a; ssum[1] = b;
            }
            __syncthreads();
            if (tid < 128) {
                float e1 = exp2f(ssum[0]), e2 = exp2f(ssum[1]);  // Q pre-scaled
                o1 += e1 * skv[tid]; o2 += e2 * skv[tid];
                L1 += e1; L2 += e2;
            }
        }
        __syncthreads();
        if (tid < 128) sres[tid] = o1 / L1 - lam * (o2 / L2);
        __syncthreads();
        if (tid == 0) {
            float s = 0, s2 = 0;
            for (int c = 0; c < 128; c++) { s += sres[c]; s2 += sres[c]*sres[c]; }
            ssum[0] = s / 128.0f;
            ssum[1] = s2 / 128.0f;
        }
        __syncthreads();
        if (tid < 128) {
            float mu = ssum[0];
            float rs = rsqrtf(ssum[1] - mu * mu + 1e-5f);
            float o = ((sres[tid] - mu) * rs * gmm + bta) * (1.0f - lambda_init);
            size_t oi = (size_t)qrow * DMODEL + h * HD2 + tid;
            __nv_bfloat16 hi = __float2bfloat16(o);
            yh[oi] = hi;
            yl[oi] = __float2bfloat16(o - __bfloat162float(hi));
        }
        __syncthreads();
    }
#endif
}

// ---------------------------------------------------------------------------
typedef CUresult (*tmap_encode_fn)(
    CUtensorMap*, CUtensorMapDataType, cuuint32_t, void*,
    const cuuint64_t*, const cuuint64_t*, const cuuint32_t*, const cuuint32_t*,
    CUtensorMapInterleave, CUtensorMapSwizzle, CUtensorMapL2promotion,
    CUtensorMapFloatOOBfill);

static void make_map_2d_t(tmap_encode_fn enc, CUtensorMap* m, void* ptr,
                          CUtensorMapDataType dt,
                          uint64_t inner, uint64_t outer, uint32_t box_outer) {
    cuuint64_t dims[2]    = {inner, outer};
    cuuint64_t strides[1] = {inner * 2};
    cuuint32_t box[2]     = {64u, box_outer};
    cuuint32_t es[2]      = {1u, 1u};
    enc(m, dt, 2, ptr, dims, strides, box, es,
        CU_TENSOR_MAP_INTERLEAVE_NONE, CU_TENSOR_MAP_SWIZZLE_128B,
        CU_TENSOR_MAP_L2_PROMOTION_L2_128B, CU_TENSOR_MAP_FLOAT_OOB_FILL_NONE);
}
static void make_map_2d(tmap_encode_fn enc, CUtensorMap* m, void* ptr,
                        uint64_t inner, uint64_t outer, uint32_t box_outer) {
    make_map_2d_t(enc, m, ptr, CU_TENSOR_MAP_DATA_TYPE_BFLOAT16,
                  inner, outer, box_outer);
}

extern "C" void kernel_launch(void* const* d_in, const int* in_sizes, int n_in,
                              void* d_out, int out_size) {
    const float* x    = (const float*)d_in[0];
    const float* Wqkv = (const float*)d_in[1];
    const float* Wo   = (const float*)d_in[2];
    const float* lq1  = (const float*)d_in[3];
    const float* lk1  = (const float*)d_in[4];
    const float* lq2  = (const float*)d_in[5];
    const float* lk2  = (const float*)d_in[6];
    const float* gg   = (const float*)d_in[7];
    const float* gb   = (const float*)d_in[8];
    float* out = (float*)d_out;

    __nv_bfloat16 *xh, *xl, *wqh, *wql, *woh, *wol, *yh, *yl;
    __nv_bfloat16 *qh, *ql, *kh, *kl;
    __half *vth, *vtl;
    cudaGetSymbolAddress((void**)&xh,  g_xh);  cudaGetSymbolAddress((void**)&xl,  g_xl);
    cudaGetSymbolAddress((void**)&wqh, g_wqh); cudaGetSymbolAddress((void**)&wql, g_wql);
    cudaGetSymbolAddress((void**)&woh, g_woh); cudaGetSymbolAddress((void**)&wol, g_wol);
    cudaGetSymbolAddress((void**)&yh,  g_yh);  cudaGetSymbolAddress((void**)&yl,  g_yl);
    cudaGetSymbolAddress((void**)&qh,  g_qh);  cudaGetSymbolAddress((void**)&ql,  g_ql);
    cudaGetSymbolAddress((void**)&kh,  g_kh);  cudaGetSymbolAddress((void**)&kl,  g_kl);
    cudaGetSymbolAddress((void**)&vth, g_vth); cudaGetSymbolAddress((void**)&vtl, g_vtl);

    tmap_encode_fn enc = nullptr;
    {
        void* p = nullptr;
        cudaDriverEntryPointQueryResult st;
        cudaGetDriverEntryPoint("cuTensorMapEncodeTiled", &p, cudaEnableDefault, &st);
        enc = (tmap_encode_fn)p;
    }

    // B boxes are 128 rows (each cg2 rank loads its own half)
    CUtensorMap mXh, mXl, mWqh, mWql, mYh, mYl, mWoh, mWol;
    make_map_2d(enc, &mXh,  xh,  DMODEL, SEQ,    128);
    make_map_2d(enc, &mXl,  xl,  DMODEL, SEQ,    128);
    make_map_2d(enc, &mWqh, wqh, DMODEL, QKVN,   128);
    make_map_2d(enc, &mWql, wql, DMODEL, QKVN,   128);
    make_map_2d(enc, &mYh,  yh,  DMODEL, SEQ,    128);
    make_map_2d(enc, &mYl,  yl,  DMODEL, SEQ,    128);
    make_map_2d(enc, &mWoh, woh, DMODEL, DMODEL, 128);
    make_map_2d(enc, &mWol, wol, DMODEL, DMODEL, 128);

    CUtensorMap mQh, mQl, mKh, mKl, mVh, mVl;
    make_map_2d(enc, &mQh, qh,  128, (uint64_t)NHEADS * SEQ, 128);
    make_map_2d(enc, &mQl, ql,  128, (uint64_t)NHEADS * SEQ, 128);
    make_map_2d(enc, &mKh, kh,  128, (uint64_t)NHEADS * SEQ, 64);
    make_map_2d(enc, &mKl, kl,  128, (uint64_t)NHEADS * SEQ, 64);
    make_map_2d_t(enc, &mVh, vth, CU_TENSOR_MAP_DATA_TYPE_FLOAT16,
                  SEQ, (uint64_t)NHEADS * 128, 128);
    make_map_2d_t(enc, &mVl, vtl, CU_TENSOR_MAP_DATA_TYPE_FLOAT16,
                  SEQ, (uint64_t)NHEADS * 128, 128);

    cudaFuncSetAttribute(gemm_qkv, cudaFuncAttributeMaxDynamicSharedMemorySize, GEMM_SMEM);
    cudaFuncSetAttribute(gemm_tma, cudaFuncAttributeMaxDynamicSharedMemorySize, GEMM_SMEM);
    cudaFuncSetAttribute(attn_tc, cudaFuncAttributeMaxDynamicSharedMemorySize, ATT_DYN);

    // 0) fused split of all GEMM operands (one launch)
    {
        int ntot = (SEQ * DMODEL + QKVN * DMODEL + DMODEL * DMODEL) / 4;
        split_all<<<(ntot + 255) / 256, 256>>>(x, Wqkv, Wo,
                                               xh, xl, wqh, wql, woh, wol);
    }

    // 1) qkv GEMM (cg2 pairs along grid.x = M) with fused split epilogue
    gemm_qkv<<<dim3(SEQ / BM, QKVN / BN), 256, GEMM_SMEM>>>(
        mXh, mXl, mWqh, mWql, xh, xl, wqh, wql,
        qh, ql, kh, kl, vth, vtl, DMODEL);

    // 2) tcgen05 differential flash attention + fused GroupNorm -> yh/yl
    attn_tc<<<dim3(SEQ / 128, NHEADS), 512, ATT_DYN>>>(
        mQh, mQl, mKh, mKl, mVh, mVl,
        qh, ql, kh, kl, vth, vtl, lq1, lk1, lq2, lk2, gg, gb, yh, yl);

    // 3) out = y @ W_o^T (cg2 pairs along grid.x = M)
    gemm_tma<<<dim3(SEQ / BM, DMODEL / BN), 256, GEMM_SMEM>>>(
        mYh, mYl, mWoh, mWol, yh, yl, woh, wol, out, DMODEL, DMODEL);
}